// round 2
// baseline (speedup 1.0000x reference)
#include <cuda_runtime.h>
#include <math.h>

#define C 128

// Max sizes per reference: N = [40000, 120000, 80000, 20000]
#define NTOT_MAX 260000
#define NMAX     120000

// Scratch: double-buffered features + GEMM temp. __device__ globals (no alloc).
__device__ float g_A[(size_t)NTOT_MAX * C];
__device__ float g_B[(size_t)NTOT_MAX * C];
__device__ float g_T[(size_t)NMAX * C];

// ---------------------------------------------------------------------------
// GEMM: Y[M,128] = X[M,128] @ W[128,128]   (fp32, smem-tiled, 8x8 microtile)
// ---------------------------------------------------------------------------
#define GEMM_SMEM_BYTES (2 * 128 * 132 * (int)sizeof(float))

__global__ __launch_bounds__(256) void gemm128_kernel(const float* __restrict__ X,
                                                      const float* __restrict__ W,
                                                      float* __restrict__ Y, int M) {
    extern __shared__ float sm[];
    float* Ws = sm;               // [k][n], padded stride 132
    float* Xs = sm + 128 * 132;   // [k][row] (transposed), padded stride 132
    const int tid  = threadIdx.x;
    const int row0 = blockIdx.x * 128;

    // Load W (128x128) -> Ws[k*132+n]
    for (int i = tid; i < 4096; i += 256) {
        int k = i >> 5, n4 = (i & 31) << 2;
        float4 w = ((const float4*)W)[i];
        *(float4*)&Ws[k * 132 + n4] = w;
    }
    // Load X tile transposed -> Xs[k*132+row]
    for (int i = tid; i < 4096; i += 256) {
        int r = i >> 5, k4 = (i & 31) << 2;
        float4 v = make_float4(0.f, 0.f, 0.f, 0.f);
        if (row0 + r < M) v = ((const float4*)(X + (size_t)(row0 + r) * C))[i & 31];
        Xs[(k4 + 0) * 132 + r] = v.x;
        Xs[(k4 + 1) * 132 + r] = v.y;
        Xs[(k4 + 2) * 132 + r] = v.z;
        Xs[(k4 + 3) * 132 + r] = v.w;
    }
    __syncthreads();

    const int tn = (tid & 15) << 3;   // col offset (0..120)
    const int tm = (tid >> 4) << 3;   // row offset (0..120)
    float acc[8][8];
#pragma unroll
    for (int i = 0; i < 8; i++)
#pragma unroll
        for (int j = 0; j < 8; j++) acc[i][j] = 0.f;

#pragma unroll 4
    for (int k = 0; k < 128; k++) {
        float a[8], b[8];
        *(float4*)&a[0] = *(const float4*)&Xs[k * 132 + tm];
        *(float4*)&a[4] = *(const float4*)&Xs[k * 132 + tm + 4];
        *(float4*)&b[0] = *(const float4*)&Ws[k * 132 + tn];
        *(float4*)&b[4] = *(const float4*)&Ws[k * 132 + tn + 4];
#pragma unroll
        for (int i = 0; i < 8; i++)
#pragma unroll
            for (int j = 0; j < 8; j++) acc[i][j] = fmaf(a[i], b[j], acc[i][j]);
    }

#pragma unroll
    for (int i = 0; i < 8; i++) {
        int r = row0 + tm + i;
        if (r < M) {
            *(float4*)&Y[(size_t)r * C + tn]     = make_float4(acc[i][0], acc[i][1], acc[i][2], acc[i][3]);
            *(float4*)&Y[(size_t)r * C + tn + 4] = make_float4(acc[i][4], acc[i][5], acc[i][6], acc[i][7]);
        }
    }
}

// ---------------------------------------------------------------------------
// SpMM scatter-add: B[row[e], :] += val[e] * T[col[e], :]   (warp per edge)
// ---------------------------------------------------------------------------
__global__ __launch_bounds__(256) void spmm_kernel(const int* __restrict__ row,
                                                   const int* __restrict__ col,
                                                   const float* __restrict__ val,
                                                   int nnz,
                                                   const float* __restrict__ T,
                                                   float* __restrict__ Bd) {
    int e = blockIdx.x * 8 + (threadIdx.x >> 5);
    if (e >= nnz) return;
    int lane = threadIdx.x & 31;
    int r = row[e];
    int c = col[e];
    float v = val[e];
    float4 t = ((const float4*)(T + (size_t)c * C))[lane];
    float* dst = Bd + (size_t)r * C + lane * 4;
    float4 u = make_float4(t.x * v, t.y * v, t.z * v, t.w * v);
    asm volatile("red.global.add.v4.f32 [%0], {%1, %2, %3, %4};"
                 :: "l"(dst), "f"(u.x), "f"(u.y), "f"(u.z), "f"(u.w)
                 : "memory");
}

// ---------------------------------------------------------------------------
// Elementwise sigmoid (in place), n multiple of 4
// ---------------------------------------------------------------------------
__global__ void sigmoid_kernel(float4* __restrict__ x, int n4) {
    int i = blockIdx.x * blockDim.x + threadIdx.x;
    if (i >= n4) return;
    float4 v = x[i];
    v.x = 1.f / (1.f + __expf(-v.x));
    v.y = 1.f / (1.f + __expf(-v.y));
    v.z = 1.f / (1.f + __expf(-v.z));
    v.w = 1.f / (1.f + __expf(-v.w));
    x[i] = v;
}

// ---------------------------------------------------------------------------
// Head: out = softmax(X0 @ W_out + b_out), warp per row, 10 outputs
// ---------------------------------------------------------------------------
__global__ __launch_bounds__(256) void head_kernel(const float* __restrict__ X,
                                                   const float* __restrict__ W,
                                                   const float* __restrict__ b,
                                                   float* __restrict__ out, int M) {
    __shared__ float Ws[1280];
    __shared__ float bs[10];
    for (int i = threadIdx.x; i < 1280; i += 256) Ws[i] = W[i];
    if (threadIdx.x < 10) bs[threadIdx.x] = b[threadIdx.x];
    __syncthreads();

    int warp = (blockIdx.x * 256 + threadIdx.x) >> 5;
    int lane = threadIdx.x & 31;
    if (warp >= M) return;

    float4 xv = ((const float4*)(X + (size_t)warp * C))[lane];
    int k = lane * 4;
    float acc[10];
#pragma unroll
    for (int o = 0; o < 10; o++) {
        acc[o] = xv.x * Ws[(k + 0) * 10 + o] + xv.y * Ws[(k + 1) * 10 + o] +
                 xv.z * Ws[(k + 2) * 10 + o] + xv.w * Ws[(k + 3) * 10 + o];
    }
#pragma unroll
    for (int s = 16; s > 0; s >>= 1)
#pragma unroll
        for (int o = 0; o < 10; o++) acc[o] += __shfl_xor_sync(0xffffffffu, acc[o], s);

    // every lane now has the full 10 logits
    float mx = -1e30f;
#pragma unroll
    for (int o = 0; o < 10; o++) { acc[o] += bs[o]; mx = fmaxf(mx, acc[o]); }
    float sum = 0.f;
    float ex[10];
#pragma unroll
    for (int o = 0; o < 10; o++) { ex[o] = __expf(acc[o] - mx); sum += ex[o]; }
    float inv = 1.f / sum;
    if (lane < 10) {
        float myv = 0.f;
#pragma unroll
        for (int o = 0; o < 10; o++)
            if (o == lane) myv = ex[o];
        out[(size_t)warp * 10 + lane] = myv * inv;
    }
}

// ---------------------------------------------------------------------------
// Host orchestration
// ---------------------------------------------------------------------------
extern "C" void kernel_launch(void* const* d_in, const int* in_sizes, int n_in,
                              void* d_out, int out_size) {
    (void)n_in; (void)out_size;
    const int L = 2;

    // ---- unpack inputs (metadata order) ----
    const float* x_in[4];
    for (int r = 0; r < 4; r++) x_in[r] = (const float*)d_in[r];
    const int*   adj_row[4]; const int* adj_col[4]; const float* adj_val[4];
    int nnz_adj[4];
    for (int r = 0; r < 4; r++) {
        adj_row[r] = (const int*)d_in[4 + 3 * r];
        adj_col[r] = (const int*)d_in[5 + 3 * r];
        adj_val[r] = (const float*)d_in[6 + 3 * r];
        nnz_adj[r] = in_sizes[4 + 3 * r];
    }
    // inc{k} for k=1..3 stored at indices 16..24
    const int*   inc_row[4]; const int* inc_col[4]; const float* inc_val[4];
    int nnz_inc[4];
    for (int k = 1; k <= 3; k++) {
        inc_row[k] = (const int*)d_in[16 + 3 * (k - 1)];
        inc_col[k] = (const int*)d_in[17 + 3 * (k - 1)];
        inc_val[k] = (const float*)d_in[18 + 3 * (k - 1)];
        nnz_inc[k] = in_sizes[16 + 3 * (k - 1)];
    }
    const float* W_same = (const float*)d_in[25]; // [L,4,128,128]
    const float* W_h2l  = (const float*)d_in[26]; // [L,3,128,128]
    const float* W_l2h  = (const float*)d_in[27]; // [L,3,128,128]
    const float* W_out  = (const float*)d_in[28]; // [128,10]
    const float* b_out  = (const float*)d_in[29]; // [10]

    int N[4];
    size_t off[4];
    size_t tot = 0;
    for (int r = 0; r < 4; r++) {
        N[r] = in_sizes[r] / C;
        off[r] = tot * (size_t)C;
        tot += (size_t)N[r];
    }

    float *A, *B, *T;
    cudaGetSymbolAddress((void**)&A, g_A);
    cudaGetSymbolAddress((void**)&B, g_B);
    cudaGetSymbolAddress((void**)&T, g_T);

    cudaFuncSetAttribute(gemm128_kernel,
                         cudaFuncAttributeMaxDynamicSharedMemorySize, GEMM_SMEM_BYTES);

    // ---- copy inputs into buffer A ----
    for (int r = 0; r < 4; r++)
        cudaMemcpyAsync(A + off[r], x_in[r], (size_t)N[r] * C * sizeof(float),
                        cudaMemcpyDeviceToDevice, 0);

    // ---- SCCN layers ----
    for (int l = 0; l < L; l++) {
        cudaMemsetAsync(B, 0, tot * (size_t)C * sizeof(float), 0);
        for (int r = 0; r < 4; r++) {
            // same-rank: adj_r @ (x_r W_same[l,r])
            {
                const float* W = W_same + ((size_t)(l * 4 + r)) * C * C;
                int M = N[r];
                gemm128_kernel<<<(M + 127) / 128, 256, GEMM_SMEM_BYTES>>>(A + off[r], W, T, M);
                spmm_kernel<<<(nnz_adj[r] + 7) / 8, 256>>>(adj_row[r], adj_col[r], adj_val[r],
                                                           nnz_adj[r], T, B + off[r]);
            }
            // high-to-low: inc_{r+1} @ (x_{r+1} W_h2l[l,r])
            if (r < 3) {
                const float* W = W_h2l + ((size_t)(l * 3 + r)) * C * C;
                int M = N[r + 1];
                gemm128_kernel<<<(M + 127) / 128, 256, GEMM_SMEM_BYTES>>>(A + off[r + 1], W, T, M);
                int k = r + 1;
                spmm_kernel<<<(nnz_inc[k] + 7) / 8, 256>>>(inc_row[k], inc_col[k], inc_val[k],
                                                           nnz_inc[k], T, B + off[r]);
            }
            // low-to-high: inc_r^T @ (x_{r-1} W_l2h[l,r-1])  (rows=icol, cols=irow)
            if (r > 0) {
                const float* W = W_l2h + ((size_t)(l * 3 + (r - 1))) * C * C;
                int M = N[r - 1];
                gemm128_kernel<<<(M + 127) / 128, 256, GEMM_SMEM_BYTES>>>(A + off[r - 1], W, T, M);
                int k = r;
                spmm_kernel<<<(nnz_inc[k] + 7) / 8, 256>>>(inc_col[k], inc_row[k], inc_val[k],
                                                           nnz_inc[k], T, B + off[r]);
            }
            // sigmoid in place on B_r
            int n4 = N[r] * C / 4;
            sigmoid_kernel<<<(n4 + 255) / 256, 256>>>((float4*)(B + off[r]), n4);
        }
        // swap buffers
        float* tmp = A; A = B; B = tmp;
    }

    // ---- output head on rank 0 ----
    {
        int M = N[0];
        int warps_per_block = 8;
        int blocks = (M + warps_per_block - 1) / warps_per_block;
        head_kernel<<<blocks, 256>>>(A + off[0], W_out, b_out, (float*)d_out, M);
    }
}

// round 5
// speedup vs baseline: 1.1924x; 1.1924x over previous
#include <cuda_runtime.h>
#include <math.h>
#include <stdint.h>

#define C 128

// Max sizes per reference: N = [40000, 120000, 80000, 20000]
#define NTOT_MAX 260000
#define NMAX     120000
#define NWMAT    20          // 8 W_same + 6 W_h2l + 6 W_l2h

// Scratch (no allocation allowed): double-buffered features + GEMM temp + W^T
__device__ float g_A[(size_t)NTOT_MAX * C];
__device__ float g_B[(size_t)NTOT_MAX * C];
__device__ float g_T[(size_t)NMAX * C];
__device__ float g_Wt[(size_t)NWMAT * C * C];

// ---------------------------------------------------------------------------
// tf32 helpers
// ---------------------------------------------------------------------------
__device__ __forceinline__ uint32_t f2tf32(float f) {
    uint32_t u;
    asm("cvt.rna.tf32.f32 %0, %1;" : "=r"(u) : "f"(f));
    return u;
}

__device__ __forceinline__ void mma_tf32(float* c, const uint32_t* a, const uint32_t* b) {
    asm volatile(
        "mma.sync.aligned.m16n8k8.row.col.f32.tf32.tf32.f32 "
        "{%0,%1,%2,%3}, {%4,%5,%6,%7}, {%8,%9}, {%0,%1,%2,%3};"
        : "+f"(c[0]), "+f"(c[1]), "+f"(c[2]), "+f"(c[3])
        : "r"(a[0]), "r"(a[1]), "r"(a[2]), "r"(a[3]), "r"(b[0]), "r"(b[1]));
}

// ---------------------------------------------------------------------------
// Transpose + tf32-round all 20 weight matrices: Wt[m][n][k] = tf32(W_m[k][n])
// ---------------------------------------------------------------------------
__global__ void wtrans_kernel(const float* __restrict__ Ws, const float* __restrict__ Wh,
                              const float* __restrict__ Wl, float* __restrict__ Wt) {
    int m = blockIdx.x;
    const float* src;
    if (m < 8)       src = Ws + (size_t)m * C * C;
    else if (m < 14) src = Wh + (size_t)(m - 8) * C * C;
    else             src = Wl + (size_t)(m - 14) * C * C;
    float* dst = Wt + (size_t)m * C * C;
    for (int i = threadIdx.x; i < C * C; i += blockDim.x) {
        int k = i >> 7, n = i & 127;
        uint32_t u = f2tf32(src[i]);
        dst[n * C + k] = __uint_as_float(u);
    }
}

// ---------------------------------------------------------------------------
// GEMM via mma.sync tf32: Y[M,128] = X[M,128] @ W[128,128]
// Wt given [n][k], pre-rounded to tf32.
// CTA = 256 threads (8 warps, 4x2), tile 128x128; warp = 32M x 64N.
// ---------------------------------------------------------------------------
#define GSTRIDE 132
#define GEMM_SMEM_BYTES (128 * GSTRIDE * 4)

__global__ __launch_bounds__(256) void gemm_mma_kernel(const float* __restrict__ X,
                                                       const float* __restrict__ Wt,
                                                       float* __restrict__ Y, int M) {
    extern __shared__ float Ws[];   // [n][k], stride GSTRIDE
    const int tid   = threadIdx.x;
    const int lane  = tid & 31;
    const int warp  = tid >> 5;
    const int warpM = warp & 3;     // 0..3
    const int warpN = warp >> 2;    // 0..1
    const int rq    = lane >> 2;    // 0..7
    const int kq    = lane & 3;     // 0..3
    const int row0  = blockIdx.x * 128 + warpM * 32;
    const int col0  = warpN * 64;

    // Stage W^T (128x128 floats, already tf32 bit patterns)
    for (int i = tid; i < 4096; i += 256) {
        int n = i >> 5, k4 = (i & 31) << 2;
        float4 v = ((const float4*)(Wt + (size_t)n * C))[i & 31];
        *(float4*)&Ws[n * GSTRIDE + k4] = v;
    }
    __syncthreads();

    // Per-thread A row pointers + validity (rows fixed across K)
    const float* pA[2][2];
    bool vA[2][2];
#pragma unroll
    for (int mt = 0; mt < 2; mt++) {
        int r0 = row0 + mt * 16 + rq;
        int r1 = r0 + 8;
        pA[mt][0] = X + (size_t)r0 * C;
        pA[mt][1] = X + (size_t)r1 * C;
        vA[mt][0] = (r0 < M);
        vA[mt][1] = (r1 < M);
    }

    float acc[2][8][4];
#pragma unroll
    for (int mt = 0; mt < 2; mt++)
#pragma unroll
        for (int nt = 0; nt < 8; nt++)
#pragma unroll
            for (int j = 0; j < 4; j++) acc[mt][nt][j] = 0.f;

#pragma unroll 2
    for (int s = 0; s < 16; s++) {
        const int k0 = s * 8;
        // A fragments (m16k8): a0=(r,k), a1=(r+8,k), a2=(r,k+4), a3=(r+8,k+4)
        uint32_t a[2][4];
#pragma unroll
        for (int mt = 0; mt < 2; mt++) {
            float f0 = vA[mt][0] ? __ldg(pA[mt][0] + k0 + kq)     : 0.f;
            float f1 = vA[mt][1] ? __ldg(pA[mt][1] + k0 + kq)     : 0.f;
            float f2 = vA[mt][0] ? __ldg(pA[mt][0] + k0 + kq + 4) : 0.f;
            float f3 = vA[mt][1] ? __ldg(pA[mt][1] + k0 + kq + 4) : 0.f;
            a[mt][0] = f2tf32(f0);
            a[mt][1] = f2tf32(f1);
            a[mt][2] = f2tf32(f2);
            a[mt][3] = f2tf32(f3);
        }
#pragma unroll
        for (int nt = 0; nt < 8; nt++) {
            // B fragment (k8n8, col-major): b0=(k,n), b1=(k+4,n), n = nbase + rq
            int n = col0 + nt * 8 + rq;
            uint32_t b[2];
            b[0] = __float_as_uint(Ws[n * GSTRIDE + k0 + kq]);
            b[1] = __float_as_uint(Ws[n * GSTRIDE + k0 + kq + 4]);
            mma_tf32(acc[0][nt], a[0], b);
            mma_tf32(acc[1][nt], a[1], b);
        }
    }

    // Store: c0,c1 -> (r, col..col+1); c2,c3 -> (r+8, col..col+1); col = 2*kq
#pragma unroll
    for (int mt = 0; mt < 2; mt++) {
        int r0 = row0 + mt * 16 + rq;
        int r1 = r0 + 8;
#pragma unroll
        for (int nt = 0; nt < 8; nt++) {
            int col = col0 + nt * 8 + 2 * kq;
            if (vA[mt][0])
                *(float2*)(Y + (size_t)r0 * C + col) = make_float2(acc[mt][nt][0], acc[mt][nt][1]);
            if (vA[mt][1])
                *(float2*)(Y + (size_t)r1 * C + col) = make_float2(acc[mt][nt][2], acc[mt][nt][3]);
        }
    }
}

// ---------------------------------------------------------------------------
// SpMM scatter-add: B[row[e], :] += val[e] * T[col[e], :]
// warp handles 4 edges (MLP=4 gathers, then 4 vector REDs)
// ---------------------------------------------------------------------------
__global__ __launch_bounds__(256) void spmm_kernel(const int* __restrict__ row,
                                                   const int* __restrict__ col,
                                                   const float* __restrict__ val,
                                                   int nnz,
                                                   const float* __restrict__ T,
                                                   float* __restrict__ Bd) {
    int warp = blockIdx.x * 8 + (threadIdx.x >> 5);
    int lane = threadIdx.x & 31;
    int e0 = warp * 4;
    if (e0 >= nnz) return;
    int cnt = nnz - e0; if (cnt > 4) cnt = 4;

    float4 t[4]; float v[4]; float* dst[4];
#pragma unroll
    for (int j = 0; j < 4; j++) {
        if (j < cnt) {
            int e = e0 + j;
            int r = __ldg(row + e);
            int c = __ldg(col + e);
            v[j] = __ldg(val + e);
            t[j] = ((const float4*)(T + (size_t)c * C))[lane];
            dst[j] = Bd + (size_t)r * C + lane * 4;
        }
    }
#pragma unroll
    for (int j = 0; j < 4; j++) {
        if (j < cnt) {
            float4 u = make_float4(t[j].x * v[j], t[j].y * v[j], t[j].z * v[j], t[j].w * v[j]);
            asm volatile("red.global.add.v4.f32 [%0], {%1, %2, %3, %4};"
                         :: "l"(dst[j]), "f"(u.x), "f"(u.y), "f"(u.z), "f"(u.w)
                         : "memory");
        }
    }
}

// ---------------------------------------------------------------------------
// Elementwise sigmoid (in place)
// ---------------------------------------------------------------------------
__global__ void sigmoid_kernel(float4* __restrict__ x, int n4) {
    int i = blockIdx.x * blockDim.x + threadIdx.x;
    if (i >= n4) return;
    float4 v = x[i];
    v.x = 1.f / (1.f + __expf(-v.x));
    v.y = 1.f / (1.f + __expf(-v.y));
    v.z = 1.f / (1.f + __expf(-v.z));
    v.w = 1.f / (1.f + __expf(-v.w));
    x[i] = v;
}

// ---------------------------------------------------------------------------
// Head: out = softmax(X0 @ W_out + b_out), warp per row, 10 outputs
// ---------------------------------------------------------------------------
__global__ __launch_bounds__(256) void head_kernel(const float* __restrict__ X,
                                                   const float* __restrict__ W,
                                                   const float* __restrict__ b,
                                                   float* __restrict__ out, int M) {
    __shared__ float Ws[1280];
    __shared__ float bs[10];
    for (int i = threadIdx.x; i < 1280; i += 256) Ws[i] = W[i];
    if (threadIdx.x < 10) bs[threadIdx.x] = b[threadIdx.x];
    __syncthreads();

    int warp = (blockIdx.x * 256 + threadIdx.x) >> 5;
    int lane = threadIdx.x & 31;
    if (warp >= M) return;

    float4 xv = ((const float4*)(X + (size_t)warp * C))[lane];
    int k = lane * 4;
    float acc[10];
#pragma unroll
    for (int o = 0; o < 10; o++) {
        acc[o] = xv.x * Ws[(k + 0) * 10 + o] + xv.y * Ws[(k + 1) * 10 + o] +
                 xv.z * Ws[(k + 2) * 10 + o] + xv.w * Ws[(k + 3) * 10 + o];
    }
#pragma unroll
    for (int s = 16; s > 0; s >>= 1)
#pragma unroll
        for (int o = 0; o < 10; o++) acc[o] += __shfl_xor_sync(0xffffffffu, acc[o], s);

    float mx = -1e30f;
#pragma unroll
    for (int o = 0; o < 10; o++) { acc[o] += bs[o]; mx = fmaxf(mx, acc[o]); }
    float sum = 0.f;
    float ex[10];
#pragma unroll
    for (int o = 0; o < 10; o++) { ex[o] = __expf(acc[o] - mx); sum += ex[o]; }
    float inv = 1.f / sum;
    if (lane < 10) {
        float myv = 0.f;
#pragma unroll
        for (int o = 0; o < 10; o++)
            if (o == lane) myv = ex[o];
        out[(size_t)warp * 10 + lane] = myv * inv;
    }
}

// ---------------------------------------------------------------------------
// Host orchestration
// ---------------------------------------------------------------------------
extern "C" void kernel_launch(void* const* d_in, const int* in_sizes, int n_in,
                              void* d_out, int out_size) {
    (void)n_in; (void)out_size;
    const int L = 2;

    const float* x_in[4];
    for (int r = 0; r < 4; r++) x_in[r] = (const float*)d_in[r];
    const int*   adj_row[4]; const int* adj_col[4]; const float* adj_val[4];
    int nnz_adj[4];
    for (int r = 0; r < 4; r++) {
        adj_row[r] = (const int*)d_in[4 + 3 * r];
        adj_col[r] = (const int*)d_in[5 + 3 * r];
        adj_val[r] = (const float*)d_in[6 + 3 * r];
        nnz_adj[r] = in_sizes[4 + 3 * r];
    }
    const int*   inc_row[4]; const int* inc_col[4]; const float* inc_val[4];
    int nnz_inc[4];
    for (int k = 1; k <= 3; k++) {
        inc_row[k] = (const int*)d_in[16 + 3 * (k - 1)];
        inc_col[k] = (const int*)d_in[17 + 3 * (k - 1)];
        inc_val[k] = (const float*)d_in[18 + 3 * (k - 1)];
        nnz_inc[k] = in_sizes[16 + 3 * (k - 1)];
    }
    const float* W_same = (const float*)d_in[25]; // [L,4,128,128]
    const float* W_h2l  = (const float*)d_in[26]; // [L,3,128,128]
    const float* W_l2h  = (const float*)d_in[27]; // [L,3,128,128]
    const float* W_out  = (const float*)d_in[28]; // [128,10]
    const float* b_out  = (const float*)d_in[29]; // [10]

    int N[4];
    size_t off[4];
    size_t tot = 0;
    for (int r = 0; r < 4; r++) {
        N[r] = in_sizes[r] / C;
        off[r] = tot * (size_t)C;
        tot += (size_t)N[r];
    }

    float *A, *B, *T, *Wt;
    cudaGetSymbolAddress((void**)&A, g_A);
    cudaGetSymbolAddress((void**)&B, g_B);
    cudaGetSymbolAddress((void**)&T, g_T);
    cudaGetSymbolAddress((void**)&Wt, g_Wt);

    cudaFuncSetAttribute(gemm_mma_kernel,
                         cudaFuncAttributeMaxDynamicSharedMemorySize, GEMM_SMEM_BYTES);

    // Pre-transpose + tf32-round all 20 weight matrices
    // (Wt index: same = l*4+r, h2l = 8 + l*3 + r, l2h = 14 + l*3 + r)
    wtrans_kernel<<<NWMAT, 256>>>(W_same, W_h2l, W_l2h, Wt);

    // copy inputs into buffer A
    for (int r = 0; r < 4; r++)
        cudaMemcpyAsync(A + off[r], x_in[r], (size_t)N[r] * C * sizeof(float),
                        cudaMemcpyDeviceToDevice, 0);

    for (int l = 0; l < L; l++) {
        cudaMemsetAsync(B, 0, tot * (size_t)C * sizeof(float), 0);
        for (int r = 0; r < 4; r++) {
            {   // same-rank: adj_r @ (x_r W_same[l,r])
                const float* w = Wt + (size_t)(l * 4 + r) * C * C;
                int M = N[r];
                gemm_mma_kernel<<<(M + 127) / 128, 256, GEMM_SMEM_BYTES>>>(A + off[r], w, T, M);
                spmm_kernel<<<(nnz_adj[r] + 31) / 32, 256>>>(adj_row[r], adj_col[r], adj_val[r],
                                                             nnz_adj[r], T, B + off[r]);
            }
            if (r < 3) {  // high-to-low: inc_{r+1} @ (x_{r+1} W_h2l[l,r])
                const float* w = Wt + (size_t)(8 + l * 3 + r) * C * C;
                int M = N[r + 1];
                gemm_mma_kernel<<<(M + 127) / 128, 256, GEMM_SMEM_BYTES>>>(A + off[r + 1], w, T, M);
                int k = r + 1;
                spmm_kernel<<<(nnz_inc[k] + 31) / 32, 256>>>(inc_row[k], inc_col[k], inc_val[k],
                                                             nnz_inc[k], T, B + off[r]);
            }
            if (r > 0) {  // low-to-high: inc_r^T @ (x_{r-1} W_l2h[l,r-1])
                const float* w = Wt + (size_t)(14 + l * 3 + (r - 1)) * C * C;
                int M = N[r - 1];
                gemm_mma_kernel<<<(M + 127) / 128, 256, GEMM_SMEM_BYTES>>>(A + off[r - 1], w, T, M);
                int k = r;
                spmm_kernel<<<(nnz_inc[k] + 31) / 32, 256>>>(inc_col[k], inc_row[k], inc_val[k],
                                                             nnz_inc[k], T, B + off[r]);
            }
            int n4 = N[r] * C / 4;
            sigmoid_kernel<<<(n4 + 255) / 256, 256>>>((float4*)(B + off[r]), n4);
        }
        float* tmp = A; A = B; B = tmp;
    }

    {
        int M = N[0];
        int blocks = (M + 7) / 8;
        head_kernel<<<blocks, 256>>>(A + off[0], W_out, b_out, (float*)d_out, M);
    }
}

// round 6
// speedup vs baseline: 1.7497x; 1.4674x over previous
#include <cuda_runtime.h>
#include <math.h>
#include <stdint.h>

#define C 128

// Max sizes per reference: N = [40000, 120000, 80000, 20000]
#define NTOT_MAX 260000
#define NMAX     120000
#define NWMAT    20          // 8 W_same + 6 W_h2l + 6 W_l2h

// Scratch (no allocation allowed)
__device__ float g_L0[(size_t)NTOT_MAX * C];   // layer-0 output (pre-sigmoid)
__device__ float g_L1[(size_t)NTOT_MAX * C];   // layer-1 output (pre-sigmoid)
__device__ float g_T[(size_t)NMAX * C];        // GEMM temp
__device__ float g_Wt[(size_t)NWMAT * C * C];  // W^T, tf32-rounded

// ---------------------------------------------------------------------------
// helpers
// ---------------------------------------------------------------------------
__device__ __forceinline__ uint32_t f2tf32(float f) {
    uint32_t u;
    asm("cvt.rna.tf32.f32 %0, %1;" : "=r"(u) : "f"(f));
    return u;
}
__device__ __forceinline__ uint32_t smem_u32(const void* p) {
    uint32_t a;
    asm("{ .reg .u64 t; cvta.to.shared.u64 t, %1; cvt.u32.u64 %0, t; }" : "=r"(a) : "l"(p));
    return a;
}
__device__ __forceinline__ void mma_tf32(float* c, const uint32_t* a, const uint32_t* b) {
    asm volatile(
        "mma.sync.aligned.m16n8k8.row.col.f32.tf32.tf32.f32 "
        "{%0,%1,%2,%3}, {%4,%5,%6,%7}, {%8,%9}, {%0,%1,%2,%3};"
        : "+f"(c[0]), "+f"(c[1]), "+f"(c[2]), "+f"(c[3])
        : "r"(a[0]), "r"(a[1]), "r"(a[2]), "r"(a[3]), "r"(b[0]), "r"(b[1]));
}
__device__ __forceinline__ void ldsm4(uint32_t* r, uint32_t addr) {
    asm volatile("ldmatrix.sync.aligned.m8n8.x4.shared.b16 {%0,%1,%2,%3}, [%4];"
                 : "=r"(r[0]), "=r"(r[1]), "=r"(r[2]), "=r"(r[3]) : "r"(addr));
}
__device__ __forceinline__ float sigmoidf_(float x) { return 1.f / (1.f + __expf(-x)); }

// ---------------------------------------------------------------------------
// Transpose + tf32-round all 20 weight matrices: Wt[m][n][k] = tf32(W_m[k][n])
// ---------------------------------------------------------------------------
__global__ void wtrans_kernel(const float* __restrict__ Ws, const float* __restrict__ Wh,
                              const float* __restrict__ Wl, float* __restrict__ Wt) {
    int m = blockIdx.x;
    const float* src;
    if (m < 8)       src = Ws + (size_t)m * C * C;
    else if (m < 14) src = Wh + (size_t)(m - 8) * C * C;
    else             src = Wl + (size_t)(m - 14) * C * C;
    float* dst = Wt + (size_t)m * C * C;
    for (int i = threadIdx.x; i < C * C; i += blockDim.x) {
        int k = i >> 7, n = i & 127;
        dst[n * C + k] = __uint_as_float(f2tf32(src[i]));
    }
}

// ---------------------------------------------------------------------------
// GEMM via mma.sync tf32 + ldmatrix: Y[M,128] = act(X)[M,128] @ W[128,128]
// Wt given [n][k], tf32-rounded. CTA = 512 threads (4x4 warps), tile 128x128.
// Warp computes 32M x 32N (2 mt x 4 nt of m16n8k8). apply_sig: sigmoid on X.
// ---------------------------------------------------------------------------
#define GSTRIDE 132
#define GEMM_SMEM_BYTES (2 * 128 * GSTRIDE * 4)   // 135168

__global__ __launch_bounds__(512) void gemm_mma_kernel(const float* __restrict__ X,
                                                       const float* __restrict__ Wt,
                                                       float* __restrict__ Y, int M,
                                                       int apply_sig) {
    extern __shared__ float sm[];
    float* Xs = sm;                      // [row][k], stride GSTRIDE
    float* Ws = sm + 128 * GSTRIDE;      // [n][k],  stride GSTRIDE
    const int tid   = threadIdx.x;
    const int lane  = tid & 31;
    const int warp  = tid >> 5;
    const int warpM = warp & 3;
    const int warpN = warp >> 2;
    const int row0  = blockIdx.x * 128;

    // Stage W^T (already tf32 bits)
    for (int i = tid; i < 4096; i += 512) {
        int n = i >> 5, c4 = i & 31;
        float4 v = ((const float4*)(Wt + (size_t)n * C))[c4];
        *(float4*)&Ws[n * GSTRIDE + c4 * 4] = v;
    }
    // Stage X tile: optional sigmoid, then tf32-round
    for (int i = tid; i < 4096; i += 512) {
        int r = i >> 5, c4 = i & 31;
        float4 v = make_float4(0.f, 0.f, 0.f, 0.f);
        if (row0 + r < M) {
            v = ((const float4*)(X + (size_t)(row0 + r) * C))[c4];
            if (apply_sig) {
                v.x = sigmoidf_(v.x); v.y = sigmoidf_(v.y);
                v.z = sigmoidf_(v.z); v.w = sigmoidf_(v.w);
            }
            v.x = __uint_as_float(f2tf32(v.x));
            v.y = __uint_as_float(f2tf32(v.y));
            v.z = __uint_as_float(f2tf32(v.z));
            v.w = __uint_as_float(f2tf32(v.w));
        }
        *(float4*)&Xs[r * GSTRIDE + c4 * 4] = v;
    }
    __syncthreads();

    // ldmatrix base addresses
    // A (x4): lanes 0-15 -> rows base+ (lane&15), k+0; lanes 16-31 -> rows base+(lane&15), k+4
    const uint32_t xs_u = smem_u32(Xs);
    const uint32_t ws_u = smem_u32(Ws);
    const int rowoffA = lane & 15;
    const int kplusA  = (lane & 16) ? 4 : 0;
    uint32_t aBase0 = xs_u + (uint32_t)(((warpM * 32 + rowoffA) * GSTRIDE + kplusA) << 2);
    uint32_t aBase1 = aBase0 + (uint32_t)(16 * GSTRIDE * 4);
    // B (x4): m0 = n0..n0+7 k0-3 (lanes0-7), m1 = same n, k4-7 (8-15),
    //         m2 = n0+8..15 k0-3 (16-23), m3 = n0+8..15 k4-7 (24-31)
    const int nrowB  = (lane & 7) + ((lane & 16) >> 1);
    const int kplusB = (lane & 8) ? 4 : 0;
    uint32_t bBase0 = ws_u + (uint32_t)(((warpN * 32 + nrowB) * GSTRIDE + kplusB) << 2);
    uint32_t bBase1 = bBase0 + (uint32_t)(16 * GSTRIDE * 4);

    float acc[2][4][4];
#pragma unroll
    for (int mt = 0; mt < 2; mt++)
#pragma unroll
        for (int nt = 0; nt < 4; nt++)
#pragma unroll
            for (int j = 0; j < 4; j++) acc[mt][nt][j] = 0.f;

#pragma unroll
    for (int s = 0; s < 16; s++) {
        uint32_t a0[4], a1[4], b0[4], b1[4];
        uint32_t koff = (uint32_t)(s * 32);   // 8 floats = 32 bytes
        ldsm4(a0, aBase0 + koff);
        ldsm4(a1, aBase1 + koff);
        ldsm4(b0, bBase0 + koff);
        ldsm4(b1, bBase1 + koff);
        // b0 = {nt0.b0, nt0.b1, nt1.b0, nt1.b1}; b1 = {nt2.., nt3..}
        mma_tf32(acc[0][0], a0, &b0[0]);
        mma_tf32(acc[0][1], a0, &b0[2]);
        mma_tf32(acc[0][2], a0, &b1[0]);
        mma_tf32(acc[0][3], a0, &b1[2]);
        mma_tf32(acc[1][0], a1, &b0[0]);
        mma_tf32(acc[1][1], a1, &b0[2]);
        mma_tf32(acc[1][2], a1, &b1[0]);
        mma_tf32(acc[1][3], a1, &b1[2]);
    }

    // Epilogue: c0,c1 -> (rq, 2kq..2kq+1); c2,c3 -> (rq+8, ..)
    const int rq = lane >> 2, kq = lane & 3;
#pragma unroll
    for (int mt = 0; mt < 2; mt++) {
        int r0 = row0 + warpM * 32 + mt * 16 + rq;
        int r1 = r0 + 8;
#pragma unroll
        for (int nt = 0; nt < 4; nt++) {
            int col = warpN * 32 + nt * 8 + 2 * kq;
            if (r0 < M)
                *(float2*)(Y + (size_t)r0 * C + col) = make_float2(acc[mt][nt][0], acc[mt][nt][1]);
            if (r1 < M)
                *(float2*)(Y + (size_t)r1 * C + col) = make_float2(acc[mt][nt][2], acc[mt][nt][3]);
        }
    }
}

// ---------------------------------------------------------------------------
// SpMM scatter-add: B[row[e], :] += val[e] * T[col[e], :]
// warp handles 4 edges (MLP=4 gathers, then 4 vector REDs)
// ---------------------------------------------------------------------------
__global__ __launch_bounds__(256) void spmm_kernel(const int* __restrict__ row,
                                                   const int* __restrict__ col,
                                                   const float* __restrict__ val,
                                                   int nnz,
                                                   const float* __restrict__ T,
                                                   float* __restrict__ Bd) {
    int warp = blockIdx.x * 8 + (threadIdx.x >> 5);
    int lane = threadIdx.x & 31;
    int e0 = warp * 4;
    if (e0 >= nnz) return;
    int cnt = nnz - e0; if (cnt > 4) cnt = 4;

    float4 t[4]; float v[4]; float* dst[4];
#pragma unroll
    for (int j = 0; j < 4; j++) {
        if (j < cnt) {
            int e = e0 + j;
            int r = __ldg(row + e);
            int c = __ldg(col + e);
            v[j] = __ldg(val + e);
            t[j] = ((const float4*)(T + (size_t)c * C))[lane];
            dst[j] = Bd + (size_t)r * C + lane * 4;
        }
    }
#pragma unroll
    for (int j = 0; j < 4; j++) {
        if (j < cnt) {
            float4 u = make_float4(t[j].x * v[j], t[j].y * v[j], t[j].z * v[j], t[j].w * v[j]);
            asm volatile("red.global.add.v4.f32 [%0], {%1, %2, %3, %4};"
                         :: "l"(dst[j]), "f"(u.x), "f"(u.y), "f"(u.z), "f"(u.w)
                         : "memory");
        }
    }
}

// ---------------------------------------------------------------------------
// Head: out = softmax(sigmoid(X0) @ W_out + b_out), warp per row
// ---------------------------------------------------------------------------
__global__ __launch_bounds__(256) void head_kernel(const float* __restrict__ X,
                                                   const float* __restrict__ W,
                                                   const float* __restrict__ b,
                                                   float* __restrict__ out, int M) {
    __shared__ float Ws[1280];
    __shared__ float bs[10];
    for (int i = threadIdx.x; i < 1280; i += 256) Ws[i] = W[i];
    if (threadIdx.x < 10) bs[threadIdx.x] = b[threadIdx.x];
    __syncthreads();

    int warp = (blockIdx.x * 256 + threadIdx.x) >> 5;
    int lane = threadIdx.x & 31;
    if (warp >= M) return;

    float4 xv = ((const float4*)(X + (size_t)warp * C))[lane];
    xv.x = sigmoidf_(xv.x); xv.y = sigmoidf_(xv.y);
    xv.z = sigmoidf_(xv.z); xv.w = sigmoidf_(xv.w);
    int k = lane * 4;
    float acc[10];
#pragma unroll
    for (int o = 0; o < 10; o++) {
        acc[o] = xv.x * Ws[(k + 0) * 10 + o] + xv.y * Ws[(k + 1) * 10 + o] +
                 xv.z * Ws[(k + 2) * 10 + o] + xv.w * Ws[(k + 3) * 10 + o];
    }
#pragma unroll
    for (int s = 16; s > 0; s >>= 1)
#pragma unroll
        for (int o = 0; o < 10; o++) acc[o] += __shfl_xor_sync(0xffffffffu, acc[o], s);

    float mx = -1e30f;
#pragma unroll
    for (int o = 0; o < 10; o++) { acc[o] += bs[o]; mx = fmaxf(mx, acc[o]); }
    float sum = 0.f;
    float ex[10];
#pragma unroll
    for (int o = 0; o < 10; o++) { ex[o] = __expf(acc[o] - mx); sum += ex[o]; }
    float inv = 1.f / sum;
    if (lane < 10) {
        float myv = 0.f;
#pragma unroll
        for (int o = 0; o < 10; o++)
            if (o == lane) myv = ex[o];
        out[(size_t)warp * 10 + lane] = myv * inv;
    }
}

// ---------------------------------------------------------------------------
// Host orchestration
// ---------------------------------------------------------------------------
extern "C" void kernel_launch(void* const* d_in, const int* in_sizes, int n_in,
                              void* d_out, int out_size) {
    (void)n_in; (void)out_size;

    const float* x_in[4];
    for (int r = 0; r < 4; r++) x_in[r] = (const float*)d_in[r];
    const int*   adj_row[4]; const int* adj_col[4]; const float* adj_val[4];
    int nnz_adj[4];
    for (int r = 0; r < 4; r++) {
        adj_row[r] = (const int*)d_in[4 + 3 * r];
        adj_col[r] = (const int*)d_in[5 + 3 * r];
        adj_val[r] = (const float*)d_in[6 + 3 * r];
        nnz_adj[r] = in_sizes[4 + 3 * r];
    }
    const int*   inc_row[4]; const int* inc_col[4]; const float* inc_val[4];
    int nnz_inc[4];
    for (int k = 1; k <= 3; k++) {
        inc_row[k] = (const int*)d_in[16 + 3 * (k - 1)];
        inc_col[k] = (const int*)d_in[17 + 3 * (k - 1)];
        inc_val[k] = (const float*)d_in[18 + 3 * (k - 1)];
        nnz_inc[k] = in_sizes[16 + 3 * (k - 1)];
    }
    const float* W_same = (const float*)d_in[25];
    const float* W_h2l  = (const float*)d_in[26];
    const float* W_l2h  = (const float*)d_in[27];
    const float* W_out  = (const float*)d_in[28];
    const float* b_out  = (const float*)d_in[29];

    int N[4];
    size_t off[4];
    size_t tot = 0;
    for (int r = 0; r < 4; r++) {
        N[r] = in_sizes[r] / C;
        off[r] = tot * (size_t)C;
        tot += (size_t)N[r];
    }

    float *L0, *L1, *T, *Wt;
    cudaGetSymbolAddress((void**)&L0, g_L0);
    cudaGetSymbolAddress((void**)&L1, g_L1);
    cudaGetSymbolAddress((void**)&T, g_T);
    cudaGetSymbolAddress((void**)&Wt, g_Wt);

    cudaFuncSetAttribute(gemm_mma_kernel,
                         cudaFuncAttributeMaxDynamicSharedMemorySize, GEMM_SMEM_BYTES);

    // Pre-transpose + tf32-round all 20 weight matrices
    // (Wt index: same = l*4+r, h2l = 8 + l*3 + r, l2h = 14 + l*3 + r)
    wtrans_kernel<<<NWMAT, 256>>>(W_same, W_h2l, W_l2h, Wt);

    for (int l = 0; l < 2; l++) {
        // Layer input: raw x (no sigmoid) for l=0; L0 (with fused sigmoid) for l=1
        const float* src[4];
        int sig = (l == 0) ? 0 : 1;
        for (int r = 0; r < 4; r++)
            src[r] = (l == 0) ? x_in[r] : (L0 + off[r]);
        float* Bcur = (l == 0) ? L0 : L1;

        cudaMemsetAsync(Bcur, 0, tot * (size_t)C * sizeof(float), 0);
        for (int r = 0; r < 4; r++) {
            {   // same-rank: adj_r @ (act(x_r) W_same[l,r])
                const float* w = Wt + (size_t)(l * 4 + r) * C * C;
                int M = N[r];
                gemm_mma_kernel<<<(M + 127) / 128, 512, GEMM_SMEM_BYTES>>>(src[r], w, T, M, sig);
                spmm_kernel<<<(nnz_adj[r] + 31) / 32, 256>>>(adj_row[r], adj_col[r], adj_val[r],
                                                             nnz_adj[r], T, Bcur + off[r]);
            }
            if (r < 3) {  // high-to-low: inc_{r+1} @ (act(x_{r+1}) W_h2l[l,r])
                const float* w = Wt + (size_t)(8 + l * 3 + r) * C * C;
                int M = N[r + 1];
                gemm_mma_kernel<<<(M + 127) / 128, 512, GEMM_SMEM_BYTES>>>(src[r + 1], w, T, M, sig);
                int k = r + 1;
                spmm_kernel<<<(nnz_inc[k] + 31) / 32, 256>>>(inc_row[k], inc_col[k], inc_val[k],
                                                             nnz_inc[k], T, Bcur + off[r]);
            }
            if (r > 0) {  // low-to-high: inc_r^T @ (act(x_{r-1}) W_l2h[l,r-1])
                const float* w = Wt + (size_t)(14 + l * 3 + (r - 1)) * C * C;
                int M = N[r - 1];
                gemm_mma_kernel<<<(M + 127) / 128, 512, GEMM_SMEM_BYTES>>>(src[r - 1], w, T, M, sig);
                int k = r;
                spmm_kernel<<<(nnz_inc[k] + 31) / 32, 256>>>(inc_col[k], inc_row[k], inc_val[k],
                                                             nnz_inc[k], T, Bcur + off[r]);
            }
        }
    }

    // head on layer-1 output (sigmoid fused inside)
    {
        int M = N[0];
        int blocks = (M + 7) / 8;
        head_kernel<<<blocks, 256>>>(L1 + off[0], W_out, b_out, (float*)d_out, M);
    }
}

// round 8
// speedup vs baseline: 1.8243x; 1.0426x over previous
#include <cuda_runtime.h>
#include <math.h>
#include <stdint.h>

#define C 128

// Max sizes per reference: N = [40000, 120000, 80000, 20000]
#define NTOT_MAX 260000
#define NMAX     120000
#define NWMAT    20          // 8 W_same + 6 W_h2l + 6 W_l2h

// Scratch (no allocation allowed)
__device__ float g_L0[(size_t)NTOT_MAX * C];   // layer-0 output (pre-sigmoid)
__device__ float g_L1[(size_t)NTOT_MAX * C];   // layer-1 output (pre-sigmoid)
__device__ float g_T0[(size_t)NMAX * C];       // GEMM temp (ping)
__device__ float g_T1[(size_t)NMAX * C];       // GEMM temp (pong)
__device__ float g_Wt[(size_t)NWMAT * C * C];  // W^T, tf32-rounded

// ---------------------------------------------------------------------------
// helpers
// ---------------------------------------------------------------------------
__device__ __forceinline__ uint32_t f2tf32(float f) {
    uint32_t u;
    asm("cvt.rna.tf32.f32 %0, %1;" : "=r"(u) : "f"(f));
    return u;
}
__device__ __forceinline__ uint32_t smem_u32(const void* p) {
    uint32_t a;
    asm("{ .reg .u64 t; cvta.to.shared.u64 t, %1; cvt.u32.u64 %0, t; }" : "=r"(a) : "l"(p));
    return a;
}
__device__ __forceinline__ void mma_tf32(float* c, const uint32_t* a, const uint32_t* b) {
    asm volatile(
        "mma.sync.aligned.m16n8k8.row.col.f32.tf32.tf32.f32 "
        "{%0,%1,%2,%3}, {%4,%5,%6,%7}, {%8,%9}, {%0,%1,%2,%3};"
        : "+f"(c[0]), "+f"(c[1]), "+f"(c[2]), "+f"(c[3])
        : "r"(a[0]), "r"(a[1]), "r"(a[2]), "r"(a[3]), "r"(b[0]), "r"(b[1]));
}
__device__ __forceinline__ void ldsm4(uint32_t* r, uint32_t addr) {
    asm volatile("ldmatrix.sync.aligned.m8n8.x4.shared.b16 {%0,%1,%2,%3}, [%4];"
                 : "=r"(r[0]), "=r"(r[1]), "=r"(r[2]), "=r"(r[3]) : "r"(addr));
}
__device__ __forceinline__ float sigmoidf_(float x) { return 1.f / (1.f + __expf(-x)); }

// ---------------------------------------------------------------------------
// Transpose + tf32-round all 20 weight matrices: Wt[m][n][k] = tf32(W_m[k][n])
// ---------------------------------------------------------------------------
__global__ void wtrans_kernel(const float* __restrict__ Ws, const float* __restrict__ Wh,
                              const float* __restrict__ Wl, float* __restrict__ Wt) {
    int m = blockIdx.x;
    const float* src;
    if (m < 8)       src = Ws + (size_t)m * C * C;
    else if (m < 14) src = Wh + (size_t)(m - 8) * C * C;
    else             src = Wl + (size_t)(m - 14) * C * C;
    float* dst = Wt + (size_t)m * C * C;
    for (int i = threadIdx.x; i < C * C; i += blockDim.x) {
        int k = i >> 7, n = i & 127;
        dst[n * C + k] = __uint_as_float(f2tf32(src[i]));
    }
}

// ---------------------------------------------------------------------------
// GEMM via mma.sync tf32 + ldmatrix: Y[M,128] = act(X)[M,128] @ W[128,128]
// Wt given [n][k], tf32-rounded. CTA = 512 threads (4x4 warps), tile 128x128.
// Warp computes 32M x 32N. Register double-buffered LDSM pipeline.
// ---------------------------------------------------------------------------
#define GSTRIDE 132
#define GEMM_SMEM_BYTES (2 * 128 * GSTRIDE * 4)   // 135168

__global__ __launch_bounds__(512) void gemm_mma_kernel(const float* __restrict__ X,
                                                       const float* __restrict__ Wt,
                                                       float* __restrict__ Y, int M,
                                                       int apply_sig) {
    extern __shared__ float sm[];
    float* Xs = sm;                      // [row][k], stride GSTRIDE
    float* Ws = sm + 128 * GSTRIDE;      // [n][k],  stride GSTRIDE
    const int tid   = threadIdx.x;
    const int lane  = tid & 31;
    const int warp  = tid >> 5;
    const int warpM = warp & 3;
    const int warpN = warp >> 2;
    const int row0  = blockIdx.x * 128;

    // Stage W^T (already tf32 bits)
    for (int i = tid; i < 4096; i += 512) {
        int n = i >> 5, c4 = i & 31;
        float4 v = ((const float4*)(Wt + (size_t)n * C))[c4];
        *(float4*)&Ws[n * GSTRIDE + c4 * 4] = v;
    }
    // Stage X tile: optional sigmoid, then tf32-round
    for (int i = tid; i < 4096; i += 512) {
        int r = i >> 5, c4 = i & 31;
        float4 v = make_float4(0.f, 0.f, 0.f, 0.f);
        if (row0 + r < M) {
            v = ((const float4*)(X + (size_t)(row0 + r) * C))[c4];
            if (apply_sig) {
                v.x = sigmoidf_(v.x); v.y = sigmoidf_(v.y);
                v.z = sigmoidf_(v.z); v.w = sigmoidf_(v.w);
            }
            v.x = __uint_as_float(f2tf32(v.x));
            v.y = __uint_as_float(f2tf32(v.y));
            v.z = __uint_as_float(f2tf32(v.z));
            v.w = __uint_as_float(f2tf32(v.w));
        }
        *(float4*)&Xs[r * GSTRIDE + c4 * 4] = v;
    }
    __syncthreads();

    // ldmatrix base addresses
    const uint32_t xs_u = smem_u32(Xs);
    const uint32_t ws_u = smem_u32(Ws);
    const int rowoffA = lane & 15;
    const int kplusA  = (lane & 16) ? 4 : 0;
    uint32_t aBase0 = xs_u + (uint32_t)(((warpM * 32 + rowoffA) * GSTRIDE + kplusA) << 2);
    uint32_t aBase1 = aBase0 + (uint32_t)(16 * GSTRIDE * 4);
    const int nrowB  = (lane & 7) + ((lane & 16) >> 1);
    const int kplusB = (lane & 8) ? 4 : 0;
    uint32_t bBase0 = ws_u + (uint32_t)(((warpN * 32 + nrowB) * GSTRIDE + kplusB) << 2);
    uint32_t bBase1 = bBase0 + (uint32_t)(16 * GSTRIDE * 4);

    float acc[2][4][4];
#pragma unroll
    for (int mt = 0; mt < 2; mt++)
#pragma unroll
        for (int nt = 0; nt < 4; nt++)
#pragma unroll
            for (int j = 0; j < 4; j++) acc[mt][nt][j] = 0.f;

    // Register double-buffered mainloop
    uint32_t fa0[2][4], fa1[2][4], fb0[2][4], fb1[2][4];
    ldsm4(fa0[0], aBase0);
    ldsm4(fa1[0], aBase1);
    ldsm4(fb0[0], bBase0);
    ldsm4(fb1[0], bBase1);
#pragma unroll
    for (int s = 0; s < 16; s++) {
        const int cur = s & 1, nxt = cur ^ 1;
        if (s < 15) {
            uint32_t koff = (uint32_t)((s + 1) * 32);   // 8 floats = 32 bytes
            ldsm4(fa0[nxt], aBase0 + koff);
            ldsm4(fa1[nxt], aBase1 + koff);
            ldsm4(fb0[nxt], bBase0 + koff);
            ldsm4(fb1[nxt], bBase1 + koff);
        }
        mma_tf32(acc[0][0], fa0[cur], &fb0[cur][0]);
        mma_tf32(acc[0][1], fa0[cur], &fb0[cur][2]);
        mma_tf32(acc[0][2], fa0[cur], &fb1[cur][0]);
        mma_tf32(acc[0][3], fa0[cur], &fb1[cur][2]);
        mma_tf32(acc[1][0], fa1[cur], &fb0[cur][0]);
        mma_tf32(acc[1][1], fa1[cur], &fb0[cur][2]);
        mma_tf32(acc[1][2], fa1[cur], &fb1[cur][0]);
        mma_tf32(acc[1][3], fa1[cur], &fb1[cur][2]);
    }

    // Epilogue
    const int rq = lane >> 2, kq = lane & 3;
#pragma unroll
    for (int mt = 0; mt < 2; mt++) {
        int r0 = row0 + warpM * 32 + mt * 16 + rq;
        int r1 = r0 + 8;
#pragma unroll
        for (int nt = 0; nt < 4; nt++) {
            int col = warpN * 32 + nt * 8 + 2 * kq;
            if (r0 < M)
                *(float2*)(Y + (size_t)r0 * C + col) = make_float2(acc[mt][nt][0], acc[mt][nt][1]);
            if (r1 < M)
                *(float2*)(Y + (size_t)r1 * C + col) = make_float2(acc[mt][nt][2], acc[mt][nt][3]);
        }
    }
}

// ---------------------------------------------------------------------------
// SpMM scatter-add: B[row[e], :] += val[e] * T[col[e], :]
// warp handles 4 edges (MLP=4 gathers, then 4 vector REDs)
// ---------------------------------------------------------------------------
__global__ __launch_bounds__(256) void spmm_kernel(const int* __restrict__ row,
                                                   const int* __restrict__ col,
                                                   const float* __restrict__ val,
                                                   int nnz,
                                                   const float* __restrict__ T,
                                                   float* __restrict__ Bd) {
    int warp = blockIdx.x * 8 + (threadIdx.x >> 5);
    int lane = threadIdx.x & 31;
    int e0 = warp * 4;
    if (e0 >= nnz) return;
    int cnt = nnz - e0; if (cnt > 4) cnt = 4;

    float4 t[4]; float v[4]; float* dst[4];
#pragma unroll
    for (int j = 0; j < 4; j++) {
        if (j < cnt) {
            int e = e0 + j;
            int r = __ldg(row + e);
            int c = __ldg(col + e);
            v[j] = __ldg(val + e);
            t[j] = ((const float4*)(T + (size_t)c * C))[lane];
            dst[j] = Bd + (size_t)r * C + lane * 4;
        }
    }
#pragma unroll
    for (int j = 0; j < 4; j++) {
        if (j < cnt) {
            float4 u = make_float4(t[j].x * v[j], t[j].y * v[j], t[j].z * v[j], t[j].w * v[j]);
            asm volatile("red.global.add.v4.f32 [%0], {%1, %2, %3, %4};"
                         :: "l"(dst[j]), "f"(u.x), "f"(u.y), "f"(u.z), "f"(u.w)
                         : "memory");
        }
    }
}

// ---------------------------------------------------------------------------
// Head: out = softmax(sigmoid(X0) @ W_out + b_out), warp per row
// ---------------------------------------------------------------------------
__global__ __launch_bounds__(256) void head_kernel(const float* __restrict__ X,
                                                   const float* __restrict__ W,
                                                   const float* __restrict__ b,
                                                   float* __restrict__ out, int M) {
    __shared__ float Ws[1280];
    __shared__ float bs[10];
    for (int i = threadIdx.x; i < 1280; i += 256) Ws[i] = W[i];
    if (threadIdx.x < 10) bs[threadIdx.x] = b[threadIdx.x];
    __syncthreads();

    int warp = (blockIdx.x * 256 + threadIdx.x) >> 5;
    int lane = threadIdx.x & 31;
    if (warp >= M) return;

    float4 xv = ((const float4*)(X + (size_t)warp * C))[lane];
    xv.x = sigmoidf_(xv.x); xv.y = sigmoidf_(xv.y);
    xv.z = sigmoidf_(xv.z); xv.w = sigmoidf_(xv.w);
    int k = lane * 4;
    float acc[10];
#pragma unroll
    for (int o = 0; o < 10; o++) {
        acc[o] = xv.x * Ws[(k + 0) * 10 + o] + xv.y * Ws[(k + 1) * 10 + o] +
                 xv.z * Ws[(k + 2) * 10 + o] + xv.w * Ws[(k + 3) * 10 + o];
    }
#pragma unroll
    for (int s = 16; s > 0; s >>= 1)
#pragma unroll
        for (int o = 0; o < 10; o++) acc[o] += __shfl_xor_sync(0xffffffffu, acc[o], s);

    float mx = -1e30f;
#pragma unroll
    for (int o = 0; o < 10; o++) { acc[o] += bs[o]; mx = fmaxf(mx, acc[o]); }
    float sum = 0.f;
    float ex[10];
#pragma unroll
    for (int o = 0; o < 10; o++) { ex[o] = __expf(acc[o] - mx); sum += ex[o]; }
    float inv = 1.f / sum;
    if (lane < 10) {
        float myv = 0.f;
#pragma unroll
        for (int o = 0; o < 10; o++)
            if (o == lane) myv = ex[o];
        out[(size_t)warp * 10 + lane] = myv * inv;
    }
}

// ---------------------------------------------------------------------------
// Host orchestration: GEMMs on stream 0, SpMMs on a forked stream, ping-pong T
// ---------------------------------------------------------------------------
extern "C" void kernel_launch(void* const* d_in, const int* in_sizes, int n_in,
                              void* d_out, int out_size) {
    (void)n_in; (void)out_size;

    // One-time host-side resources (created on first, uncaptured call; no device alloc)
    static cudaStream_t s1 = nullptr;
    static cudaEvent_t evFork, evJoin, evG[20], evS[20];
    if (!s1) {
        cudaStreamCreateWithFlags(&s1, cudaStreamNonBlocking);
        cudaEventCreateWithFlags(&evFork, cudaEventDisableTiming);
        cudaEventCreateWithFlags(&evJoin, cudaEventDisableTiming);
        for (int i = 0; i < 20; i++) {
            cudaEventCreateWithFlags(&evG[i], cudaEventDisableTiming);
            cudaEventCreateWithFlags(&evS[i], cudaEventDisableTiming);
        }
    }

    const float* x_in[4];
    for (int r = 0; r < 4; r++) x_in[r] = (const float*)d_in[r];
    const int*   adj_row[4]; const int* adj_col[4]; const float* adj_val[4];
    int nnz_adj[4];
    for (int r = 0; r < 4; r++) {
        adj_row[r] = (const int*)d_in[4 + 3 * r];
        adj_col[r] = (const int*)d_in[5 + 3 * r];
        adj_val[r] = (const float*)d_in[6 + 3 * r];
        nnz_adj[r] = in_sizes[4 + 3 * r];
    }
    const int*   inc_row[4]; const int* inc_col[4]; const float* inc_val[4];
    int nnz_inc[4];
    for (int k = 1; k <= 3; k++) {
        inc_row[k] = (const int*)d_in[16 + 3 * (k - 1)];
        inc_col[k] = (const int*)d_in[17 + 3 * (k - 1)];
        inc_val[k] = (const float*)d_in[18 + 3 * (k - 1)];
        nnz_inc[k] = in_sizes[16 + 3 * (k - 1)];
    }
    const float* W_same = (const float*)d_in[25];
    const float* W_h2l  = (const float*)d_in[26];
    const float* W_l2h  = (const float*)d_in[27];
    const float* W_out  = (const float*)d_in[28];
    const float* b_out  = (const float*)d_in[29];

    int N[4];
    size_t off[4];
    size_t tot = 0;
    for (int r = 0; r < 4; r++) {
        N[r] = in_sizes[r] / C;
        off[r] = tot * (size_t)C;
        tot += (size_t)N[r];
    }

    float *L0, *L1, *T0, *T1, *Wt;
    cudaGetSymbolAddress((void**)&L0, g_L0);
    cudaGetSymbolAddress((void**)&L1, g_L1);
    cudaGetSymbolAddress((void**)&T0, g_T0);
    cudaGetSymbolAddress((void**)&T1, g_T1);
    cudaGetSymbolAddress((void**)&Wt, g_Wt);
    float* Tbuf[2] = {T0, T1};

    cudaFuncSetAttribute(gemm_mma_kernel,
                         cudaFuncAttributeMaxDynamicSharedMemorySize, GEMM_SMEM_BYTES);

    // W transpose (stream 0, precedes all GEMMs in-order)
    wtrans_kernel<<<NWMAT, 256>>>(W_same, W_h2l, W_l2h, Wt);

    // Fork spmm stream
    cudaEventRecord(evFork, 0);
    cudaStreamWaitEvent(s1, evFork, 0);

    int idx = 0;
    for (int l = 0; l < 2; l++) {
        const float* src[4];
        int sig = (l == 0) ? 0 : 1;
        for (int r = 0; r < 4; r++)
            src[r] = (l == 0) ? x_in[r] : (L0 + off[r]);
        float* Bcur = (l == 0) ? L0 : L1;

        // zero destination (on s1, in-order before this layer's spmms)
        cudaMemsetAsync(Bcur, 0, tot * (size_t)C * sizeof(float), s1);

        // Layer-1 GEMMs read L0 which layer-0 spmms produced on s1
        if (l == 1) cudaStreamWaitEvent(0, evS[9], 0);

        for (int r = 0; r < 4; r++) {
            // (gemm_src_row0, weight, spmm rows/cols/vals/nnz)
            struct Branch { const float* x; const float* w; int M;
                            const int* er; const int* ec; const float* ev; int nnz; };
            Branch br[3]; int nb = 0;
            {   // same-rank
                br[nb++] = { src[r], Wt + (size_t)(l * 4 + r) * C * C, N[r],
                             adj_row[r], adj_col[r], adj_val[r], nnz_adj[r] };
            }
            if (r < 3) {  // high-to-low
                int k = r + 1;
                br[nb++] = { src[r + 1], Wt + (size_t)(8 + l * 3 + r) * C * C, N[r + 1],
                             inc_row[k], inc_col[k], inc_val[k], nnz_inc[k] };
            }
            if (r > 0) {  // low-to-high (transposed incidence)
                int k = r;
                br[nb++] = { src[r - 1], Wt + (size_t)(14 + l * 3 + (r - 1)) * C * C, N[r - 1],
                             inc_col[k], inc_row[k], inc_val[k], nnz_inc[k] };
            }
            for (int b = 0; b < nb; b++) {
                float* T = Tbuf[idx & 1];
                if (idx >= 2) cudaStreamWaitEvent(0, evS[idx - 2], 0);  // T reuse
                gemm_mma_kernel<<<(br[b].M + 127) / 128, 512, GEMM_SMEM_BYTES>>>(
                    br[b].x, br[b].w, T, br[b].M, sig);
                cudaEventRecord(evG[idx], 0);
                cudaStreamWaitEvent(s1, evG[idx], 0);
                spmm_kernel<<<(br[b].nnz + 31) / 32, 256, 0, s1>>>(
                    br[b].er, br[b].ec, br[b].ev, br[b].nnz, T, Bcur + off[r]);
                cudaEventRecord(evS[idx], s1);
                idx++;
            }
        }
    }

    // Join and run head
    cudaEventRecord(evJoin, s1);
    cudaStreamWaitEvent(0, evJoin, 0);
    {
        int M = N[0];
        int blocks = (M + 7) / 8;
        head_kernel<<<blocks, 256>>>(L1 + off[0], W_out, b_out, (float*)d_out, M);
    }
}

// round 10
// speedup vs baseline: 1.9327x; 1.0594x over previous
#include <cuda_runtime.h>
#include <cuda_bf16.h>
#include <math.h>
#include <stdint.h>

#define C 128

// Max sizes per reference: N = [40000, 120000, 80000, 20000]
#define NTOT_MAX 260000
#define NMAX     120000
#define NWMAT    20          // 8 W_same + 6 W_h2l + 6 W_l2h

// Scratch (no allocation allowed)
__device__ float g_L0[(size_t)NTOT_MAX * C];          // layer-0 output (pre-sigmoid)
__device__ float g_L1[(size_t)NTOT_MAX * C];          // layer-1 output (pre-sigmoid)
__device__ __nv_bfloat16 g_T0[(size_t)NMAX * C];      // GEMM temp (ping), bf16
__device__ __nv_bfloat16 g_T1[(size_t)NMAX * C];      // GEMM temp (pong), bf16
__device__ float g_Wt[(size_t)NWMAT * C * C];         // W^T, tf32-rounded

// ---------------------------------------------------------------------------
// helpers
// ---------------------------------------------------------------------------
__device__ __forceinline__ uint32_t f2tf32(float f) {
    uint32_t u;
    asm("cvt.rna.tf32.f32 %0, %1;" : "=r"(u) : "f"(f));
    return u;
}
__device__ __forceinline__ uint32_t smem_u32(const void* p) {
    uint32_t a;
    asm("{ .reg .u64 t; cvta.to.shared.u64 t, %1; cvt.u32.u64 %0, t; }" : "=r"(a) : "l"(p));
    return a;
}
__device__ __forceinline__ void mma_tf32(float* c, const uint32_t* a, const uint32_t* b) {
    asm volatile(
        "mma.sync.aligned.m16n8k8.row.col.f32.tf32.tf32.f32 "
        "{%0,%1,%2,%3}, {%4,%5,%6,%7}, {%8,%9}, {%0,%1,%2,%3};"
        : "+f"(c[0]), "+f"(c[1]), "+f"(c[2]), "+f"(c[3])
        : "r"(a[0]), "r"(a[1]), "r"(a[2]), "r"(a[3]), "r"(b[0]), "r"(b[1]));
}
__device__ __forceinline__ void ldsm4(uint32_t* r, uint32_t addr) {
    asm volatile("ldmatrix.sync.aligned.m8n8.x4.shared.b16 {%0,%1,%2,%3}, [%4];"
                 : "=r"(r[0]), "=r"(r[1]), "=r"(r[2]), "=r"(r[3]) : "r"(addr));
}
__device__ __forceinline__ float sigmoidf_(float x) { return 1.f / (1.f + __expf(-x)); }

// ---------------------------------------------------------------------------
// Transpose + tf32-round all 20 weight matrices: Wt[m][n][k] = tf32(W_m[k][n])
// ---------------------------------------------------------------------------
__global__ void wtrans_kernel(const float* __restrict__ Ws, const float* __restrict__ Wh,
                              const float* __restrict__ Wl, float* __restrict__ Wt) {
    int m = blockIdx.x;
    const float* src;
    if (m < 8)       src = Ws + (size_t)m * C * C;
    else if (m < 14) src = Wh + (size_t)(m - 8) * C * C;
    else             src = Wl + (size_t)(m - 14) * C * C;
    float* dst = Wt + (size_t)m * C * C;
    for (int i = threadIdx.x; i < C * C; i += blockDim.x) {
        int k = i >> 7, n = i & 127;
        dst[n * C + k] = __uint_as_float(f2tf32(src[i]));
    }
}

// ---------------------------------------------------------------------------
// GEMM via mma.sync tf32 + ldmatrix: Y[M,128](bf16) = act(X)[M,128] @ W[128,128]
// Wt given [n][k], tf32-rounded. CTA = 512 threads (4x4 warps), tile 128x128.
// Warp computes 32M x 32N. Register double-buffered LDSM pipeline.
// ---------------------------------------------------------------------------
#define GSTRIDE 132
#define GEMM_SMEM_BYTES (2 * 128 * GSTRIDE * 4)   // 135168

__global__ __launch_bounds__(512) void gemm_mma_kernel(const float* __restrict__ X,
                                                       const float* __restrict__ Wt,
                                                       __nv_bfloat16* __restrict__ Y, int M,
                                                       int apply_sig) {
    extern __shared__ float sm[];
    float* Xs = sm;                      // [row][k], stride GSTRIDE
    float* Ws = sm + 128 * GSTRIDE;      // [n][k],  stride GSTRIDE
    const int tid   = threadIdx.x;
    const int lane  = tid & 31;
    const int warp  = tid >> 5;
    const int warpM = warp & 3;
    const int warpN = warp >> 2;
    const int row0  = blockIdx.x * 128;

    // Stage W^T (already tf32 bits)
    for (int i = tid; i < 4096; i += 512) {
        int n = i >> 5, c4 = i & 31;
        float4 v = ((const float4*)(Wt + (size_t)n * C))[c4];
        *(float4*)&Ws[n * GSTRIDE + c4 * 4] = v;
    }
    // Stage X tile: optional sigmoid, then tf32-round
    for (int i = tid; i < 4096; i += 512) {
        int r = i >> 5, c4 = i & 31;
        float4 v = make_float4(0.f, 0.f, 0.f, 0.f);
        if (row0 + r < M) {
            v = ((const float4*)(X + (size_t)(row0 + r) * C))[c4];
            if (apply_sig) {
                v.x = sigmoidf_(v.x); v.y = sigmoidf_(v.y);
                v.z = sigmoidf_(v.z); v.w = sigmoidf_(v.w);
            }
            v.x = __uint_as_float(f2tf32(v.x));
            v.y = __uint_as_float(f2tf32(v.y));
            v.z = __uint_as_float(f2tf32(v.z));
            v.w = __uint_as_float(f2tf32(v.w));
        }
        *(float4*)&Xs[r * GSTRIDE + c4 * 4] = v;
    }
    __syncthreads();

    // ldmatrix base addresses
    const uint32_t xs_u = smem_u32(Xs);
    const uint32_t ws_u = smem_u32(Ws);
    const int rowoffA = lane & 15;
    const int kplusA  = (lane & 16) ? 4 : 0;
    uint32_t aBase0 = xs_u + (uint32_t)(((warpM * 32 + rowoffA) * GSTRIDE + kplusA) << 2);
    uint32_t aBase1 = aBase0 + (uint32_t)(16 * GSTRIDE * 4);
    const int nrowB  = (lane & 7) + ((lane & 16) >> 1);
    const int kplusB = (lane & 8) ? 4 : 0;
    uint32_t bBase0 = ws_u + (uint32_t)(((warpN * 32 + nrowB) * GSTRIDE + kplusB) << 2);
    uint32_t bBase1 = bBase0 + (uint32_t)(16 * GSTRIDE * 4);

    float acc[2][4][4];
#pragma unroll
    for (int mt = 0; mt < 2; mt++)
#pragma unroll
        for (int nt = 0; nt < 4; nt++)
#pragma unroll
            for (int j = 0; j < 4; j++) acc[mt][nt][j] = 0.f;

    // Register double-buffered mainloop
    uint32_t fa0[2][4], fa1[2][4], fb0[2][4], fb1[2][4];
    ldsm4(fa0[0], aBase0);
    ldsm4(fa1[0], aBase1);
    ldsm4(fb0[0], bBase0);
    ldsm4(fb1[0], bBase1);
#pragma unroll
    for (int s = 0; s < 16; s++) {
        const int cur = s & 1, nxt = cur ^ 1;
        if (s < 15) {
            uint32_t koff = (uint32_t)((s + 1) * 32);   // 8 floats = 32 bytes
            ldsm4(fa0[nxt], aBase0 + koff);
            ldsm4(fa1[nxt], aBase1 + koff);
            ldsm4(fb0[nxt], bBase0 + koff);
            ldsm4(fb1[nxt], bBase1 + koff);
        }
        mma_tf32(acc[0][0], fa0[cur], &fb0[cur][0]);
        mma_tf32(acc[0][1], fa0[cur], &fb0[cur][2]);
        mma_tf32(acc[0][2], fa0[cur], &fb1[cur][0]);
        mma_tf32(acc[0][3], fa0[cur], &fb1[cur][2]);
        mma_tf32(acc[1][0], fa1[cur], &fb0[cur][0]);
        mma_tf32(acc[1][1], fa1[cur], &fb0[cur][2]);
        mma_tf32(acc[1][2], fa1[cur], &fb1[cur][0]);
        mma_tf32(acc[1][3], fa1[cur], &fb1[cur][2]);
    }

    // Epilogue: bf16x2 stores. c0,c1 -> (rq, 2kq..2kq+1); c2,c3 -> (rq+8, ..)
    const int rq = lane >> 2, kq = lane & 3;
#pragma unroll
    for (int mt = 0; mt < 2; mt++) {
        int r0 = row0 + warpM * 32 + mt * 16 + rq;
        int r1 = r0 + 8;
#pragma unroll
        for (int nt = 0; nt < 4; nt++) {
            int col = warpN * 32 + nt * 8 + 2 * kq;
            if (r0 < M)
                *(__nv_bfloat162*)(Y + (size_t)r0 * C + col) =
                    __float22bfloat162_rn(make_float2(acc[mt][nt][0], acc[mt][nt][1]));
            if (r1 < M)
                *(__nv_bfloat162*)(Y + (size_t)r1 * C + col) =
                    __float22bfloat162_rn(make_float2(acc[mt][nt][2], acc[mt][nt][3]));
        }
    }
}

// ---------------------------------------------------------------------------
// SpMM scatter-add: B[row[e], :] += val[e] * T[col[e], :]   (T is bf16)
// warp handles 4 edges (MLP=4 gathers, then 4 vector REDs)
// ---------------------------------------------------------------------------
__global__ __launch_bounds__(256) void spmm_kernel(const int* __restrict__ row,
                                                   const int* __restrict__ col,
                                                   const float* __restrict__ val,
                                                   int nnz,
                                                   const __nv_bfloat16* __restrict__ T,
                                                   float* __restrict__ Bd) {
    int warp = blockIdx.x * 8 + (threadIdx.x >> 5);
    int lane = threadIdx.x & 31;
    int e0 = warp * 4;
    if (e0 >= nnz) return;
    int cnt = nnz - e0; if (cnt > 4) cnt = 4;

    uint2 t[4]; float v[4]; float* dst[4];
#pragma unroll
    for (int j = 0; j < 4; j++) {
        if (j < cnt) {
            int e = e0 + j;
            int r = __ldg(row + e);
            int c = __ldg(col + e);
            v[j] = __ldg(val + e);
            t[j] = ((const uint2*)(T + (size_t)c * C))[lane];   // 4 bf16 = 8 bytes
            dst[j] = Bd + (size_t)r * C + lane * 4;
        }
    }
#pragma unroll
    for (int j = 0; j < 4; j++) {
        if (j < cnt) {
            float2 f0 = __bfloat1622float2(*(const __nv_bfloat162*)&t[j].x);
            float2 f1 = __bfloat1622float2(*(const __nv_bfloat162*)&t[j].y);
            float4 u = make_float4(f0.x * v[j], f0.y * v[j], f1.x * v[j], f1.y * v[j]);
            asm volatile("red.global.add.v4.f32 [%0], {%1, %2, %3, %4};"
                         :: "l"(dst[j]), "f"(u.x), "f"(u.y), "f"(u.z), "f"(u.w)
                         : "memory");
        }
    }
}

// ---------------------------------------------------------------------------
// Head: out = softmax(sigmoid(X0) @ W_out + b_out), warp per row
// ---------------------------------------------------------------------------
__global__ __launch_bounds__(256) void head_kernel(const float* __restrict__ X,
                                                   const float* __restrict__ W,
                                                   const float* __restrict__ b,
                                                   float* __restrict__ out, int M) {
    __shared__ float Ws[1280];
    __shared__ float bs[10];
    for (int i = threadIdx.x; i < 1280; i += 256) Ws[i] = W[i];
    if (threadIdx.x < 10) bs[threadIdx.x] = b[threadIdx.x];
    __syncthreads();

    int warp = (blockIdx.x * 256 + threadIdx.x) >> 5;
    int lane = threadIdx.x & 31;
    if (warp >= M) return;

    float4 xv = ((const float4*)(X + (size_t)warp * C))[lane];
    xv.x = sigmoidf_(xv.x); xv.y = sigmoidf_(xv.y);
    xv.z = sigmoidf_(xv.z); xv.w = sigmoidf_(xv.w);
    int k = lane * 4;
    float acc[10];
#pragma unroll
    for (int o = 0; o < 10; o++) {
        acc[o] = xv.x * Ws[(k + 0) * 10 + o] + xv.y * Ws[(k + 1) * 10 + o] +
                 xv.z * Ws[(k + 2) * 10 + o] + xv.w * Ws[(k + 3) * 10 + o];
    }
#pragma unroll
    for (int s = 16; s > 0; s >>= 1)
#pragma unroll
        for (int o = 0; o < 10; o++) acc[o] += __shfl_xor_sync(0xffffffffu, acc[o], s);

    float mx = -1e30f;
#pragma unroll
    for (int o = 0; o < 10; o++) { acc[o] += bs[o]; mx = fmaxf(mx, acc[o]); }
    float sum = 0.f;
    float ex[10];
#pragma unroll
    for (int o = 0; o < 10; o++) { ex[o] = __expf(acc[o] - mx); sum += ex[o]; }
    float inv = 1.f / sum;
    if (lane < 10) {
        float myv = 0.f;
#pragma unroll
        for (int o = 0; o < 10; o++)
            if (o == lane) myv = ex[o];
        out[(size_t)warp * 10 + lane] = myv * inv;
    }
}

// ---------------------------------------------------------------------------
// Host orchestration: GEMMs on stream 0, SpMMs on a forked stream, ping-pong T
// ---------------------------------------------------------------------------
extern "C" void kernel_launch(void* const* d_in, const int* in_sizes, int n_in,
                              void* d_out, int out_size) {
    (void)n_in; (void)out_size;

    // One-time host-side resources (created on first, uncaptured call; no device alloc)
    static cudaStream_t s1 = nullptr;
    static cudaEvent_t evFork, evJoin, evG[20], evS[20];
    if (!s1) {
        cudaStreamCreateWithFlags(&s1, cudaStreamNonBlocking);
        cudaEventCreateWithFlags(&evFork, cudaEventDisableTiming);
        cudaEventCreateWithFlags(&evJoin, cudaEventDisableTiming);
        for (int i = 0; i < 20; i++) {
            cudaEventCreateWithFlags(&evG[i], cudaEventDisableTiming);
            cudaEventCreateWithFlags(&evS[i], cudaEventDisableTiming);
        }
    }

    const float* x_in[4];
    for (int r = 0; r < 4; r++) x_in[r] = (const float*)d_in[r];
    const int*   adj_row[4]; const int* adj_col[4]; const float* adj_val[4];
    int nnz_adj[4];
    for (int r = 0; r < 4; r++) {
        adj_row[r] = (const int*)d_in[4 + 3 * r];
        adj_col[r] = (const int*)d_in[5 + 3 * r];
        adj_val[r] = (const float*)d_in[6 + 3 * r];
        nnz_adj[r] = in_sizes[4 + 3 * r];
    }
    const int*   inc_row[4]; const int* inc_col[4]; const float* inc_val[4];
    int nnz_inc[4];
    for (int k = 1; k <= 3; k++) {
        inc_row[k] = (const int*)d_in[16 + 3 * (k - 1)];
        inc_col[k] = (const int*)d_in[17 + 3 * (k - 1)];
        inc_val[k] = (const float*)d_in[18 + 3 * (k - 1)];
        nnz_inc[k] = in_sizes[16 + 3 * (k - 1)];
    }
    const float* W_same = (const float*)d_in[25];
    const float* W_h2l  = (const float*)d_in[26];
    const float* W_l2h  = (const float*)d_in[27];
    const float* W_out  = (const float*)d_in[28];
    const float* b_out  = (const float*)d_in[29];

    int N[4];
    size_t off[4];
    size_t tot = 0;
    for (int r = 0; r < 4; r++) {
        N[r] = in_sizes[r] / C;
        off[r] = tot * (size_t)C;
        tot += (size_t)N[r];
    }

    float *L0, *L1, *Wt;
    __nv_bfloat16 *T0, *T1;
    cudaGetSymbolAddress((void**)&L0, g_L0);
    cudaGetSymbolAddress((void**)&L1, g_L1);
    cudaGetSymbolAddress((void**)&T0, g_T0);
    cudaGetSymbolAddress((void**)&T1, g_T1);
    cudaGetSymbolAddress((void**)&Wt, g_Wt);
    __nv_bfloat16* Tbuf[2] = {T0, T1};

    cudaFuncSetAttribute(gemm_mma_kernel,
                         cudaFuncAttributeMaxDynamicSharedMemorySize, GEMM_SMEM_BYTES);

    // W transpose (stream 0, precedes all GEMMs in-order)
    wtrans_kernel<<<NWMAT, 256>>>(W_same, W_h2l, W_l2h, Wt);

    // Fork spmm stream; hoist both layer-destination memsets (hide under GEMMs)
    cudaEventRecord(evFork, 0);
    cudaStreamWaitEvent(s1, evFork, 0);
    cudaMemsetAsync(L0, 0, tot * (size_t)C * sizeof(float), s1);
    cudaMemsetAsync(L1, 0, tot * (size_t)C * sizeof(float), s1);

    int idx = 0;
    for (int l = 0; l < 2; l++) {
        const float* src[4];
        int sig = (l == 0) ? 0 : 1;
        for (int r = 0; r < 4; r++)
            src[r] = (l == 0) ? x_in[r] : (L0 + off[r]);
        float* Bcur = (l == 0) ? L0 : L1;

        // Layer-1 GEMMs read L0 which layer-0 spmms produced on s1
        if (l == 1) cudaStreamWaitEvent(0, evS[9], 0);

        for (int r = 0; r < 4; r++) {
            struct Branch { const float* x; const float* w; int M;
                            const int* er; const int* ec; const float* ev; int nnz; };
            Branch br[3]; int nb = 0;
            {   // same-rank
                br[nb++] = { src[r], Wt + (size_t)(l * 4 + r) * C * C, N[r],
                             adj_row[r], adj_col[r], adj_val[r], nnz_adj[r] };
            }
            if (r < 3) {  // high-to-low
                int k = r + 1;
                br[nb++] = { src[r + 1], Wt + (size_t)(8 + l * 3 + r) * C * C, N[r + 1],
                             inc_row[k], inc_col[k], inc_val[k], nnz_inc[k] };
            }
            if (r > 0) {  // low-to-high (transposed incidence)
                int k = r;
                br[nb++] = { src[r - 1], Wt + (size_t)(14 + l * 3 + (r - 1)) * C * C, N[r - 1],
                             inc_col[k], inc_row[k], inc_val[k], nnz_inc[k] };
            }
            for (int b = 0; b < nb; b++) {
                __nv_bfloat16* T = Tbuf[idx & 1];
                if (idx >= 2) cudaStreamWaitEvent(0, evS[idx - 2], 0);  // T reuse
                gemm_mma_kernel<<<(br[b].M + 127) / 128, 512, GEMM_SMEM_BYTES>>>(
                    br[b].x, br[b].w, T, br[b].M, sig);
                cudaEventRecord(evG[idx], 0);
                cudaStreamWaitEvent(s1, evG[idx], 0);
                spmm_kernel<<<(br[b].nnz + 31) / 32, 256, 0, s1>>>(
                    br[b].er, br[b].ec, br[b].ev, br[b].nnz, T, Bcur + off[r]);
                cudaEventRecord(evS[idx], s1);
                idx++;
            }
        }
    }

    // Join and run head
    cudaEventRecord(evJoin, s1);
    cudaStreamWaitEvent(0, evJoin, 0);
    {
        int M = N[0];
        int blocks = (M + 7) / 8;
        head_kernel<<<blocks, 256>>>(L1 + off[0], W_out, b_out, (float*)d_out, M);
    }
}

// round 12
// speedup vs baseline: 2.2181x; 1.1477x over previous
#include <cuda_runtime.h>
#include <cuda_bf16.h>
#include <math.h>
#include <stdint.h>

#define C 128

// Max sizes per reference: N = [40000, 120000, 80000, 20000]
#define NTOT_MAX 260000
#define NMAX     120000
#define NWMAT    20          // 8 W_same + 6 W_h2l + 6 W_l2h

// Scratch (no allocation allowed)
__device__ float g_L0[(size_t)NTOT_MAX * C];             // layer-0 output (pre-sigmoid)
__device__ float g_L1[(size_t)NTOT_MAX * C];             // layer-1 output (pre-sigmoid)
__device__ __nv_bfloat16 g_T[4][(size_t)NMAX * C];       // GEMM temp ring, bf16
__device__ __nv_bfloat16 g_Wt[(size_t)NWMAT * C * C];    // W^T, bf16

// ---------------------------------------------------------------------------
// helpers
// ---------------------------------------------------------------------------
__device__ __forceinline__ uint32_t smem_u32(const void* p) {
    uint32_t a;
    asm("{ .reg .u64 t; cvta.to.shared.u64 t, %1; cvt.u32.u64 %0, t; }" : "=r"(a) : "l"(p));
    return a;
}
__device__ __forceinline__ void mma_bf16(float* c, const uint32_t* a, const uint32_t* b) {
    asm volatile(
        "mma.sync.aligned.m16n8k16.row.col.f32.bf16.bf16.f32 "
        "{%0,%1,%2,%3}, {%4,%5,%6,%7}, {%8,%9}, {%0,%1,%2,%3};"
        : "+f"(c[0]), "+f"(c[1]), "+f"(c[2]), "+f"(c[3])
        : "r"(a[0]), "r"(a[1]), "r"(a[2]), "r"(a[3]), "r"(b[0]), "r"(b[1]));
}
__device__ __forceinline__ void ldsm4(uint32_t* r, uint32_t addr) {
    asm volatile("ldmatrix.sync.aligned.m8n8.x4.shared.b16 {%0,%1,%2,%3}, [%4];"
                 : "=r"(r[0]), "=r"(r[1]), "=r"(r[2]), "=r"(r[3]) : "r"(addr));
}
__device__ __forceinline__ float sigmoidf_(float x) { return 1.f / (1.f + __expf(-x)); }

// ---------------------------------------------------------------------------
// Transpose + bf16-convert all 20 weight matrices: Wt[m][n][k] = bf16(W_m[k][n])
// ---------------------------------------------------------------------------
__global__ void wtrans_kernel(const float* __restrict__ Ws, const float* __restrict__ Wh,
                              const float* __restrict__ Wl, __nv_bfloat16* __restrict__ Wt) {
    int m = blockIdx.x;
    const float* src;
    if (m < 8)       src = Ws + (size_t)m * C * C;
    else if (m < 14) src = Wh + (size_t)(m - 8) * C * C;
    else             src = Wl + (size_t)(m - 14) * C * C;
    __nv_bfloat16* dst = Wt + (size_t)m * C * C;
    for (int i = threadIdx.x; i < C * C; i += blockDim.x) {
        int k = i >> 7, n = i & 127;
        dst[n * C + k] = __float2bfloat16(src[i]);
    }
}

// ---------------------------------------------------------------------------
// GEMM via mma.sync bf16 + ldmatrix: Y[M,128](bf16) = act(X)[M,128] @ W[128,128]
// Wt given [n][k] bf16. CTA = 512 threads (4x4 warps), tile 128x128.
// Warp computes 32M x 32N via m16n8k16. Register double-buffered LDSM pipeline.
// smem row stride 272B (136 bf16): conflict-free ldmatrix (68 mod 32 = 4).
// ---------------------------------------------------------------------------
#define RSTRIDE_B 272
#define GEMM_SMEM_BYTES (2 * 128 * RSTRIDE_B)   // 69632

__global__ __launch_bounds__(512) void gemm_mma_kernel(const float* __restrict__ X,
                                                       const __nv_bfloat16* __restrict__ Wt,
                                                       __nv_bfloat16* __restrict__ Y, int M,
                                                       int apply_sig) {
    extern __shared__ char smc[];
    char* Xs = smc;                       // [row][k] bf16, stride 272B
    char* Ws = smc + 128 * RSTRIDE_B;     // [n][k]  bf16, stride 272B
    const int tid   = threadIdx.x;
    const int lane  = tid & 31;
    const int warp  = tid >> 5;
    const int warpM = warp & 3;
    const int warpN = warp >> 2;
    const int row0  = blockIdx.x * 128;

    // Stage W^T (bf16, 8B chunks = 4 bf16)
    for (int i = tid; i < 4096; i += 512) {
        int n = i >> 5, c = i & 31;
        uint2 v = ((const uint2*)(Wt + (size_t)n * C))[c];
        *(uint2*)(Ws + n * RSTRIDE_B + c * 8) = v;
    }
    // Stage X tile: optional sigmoid, convert fp32 -> bf16
    for (int i = tid; i < 4096; i += 512) {
        int r = i >> 5, c = i & 31;
        float4 v = make_float4(0.f, 0.f, 0.f, 0.f);
        if (row0 + r < M) {
            v = ((const float4*)(X + (size_t)(row0 + r) * C))[c];
            if (apply_sig) {
                v.x = sigmoidf_(v.x); v.y = sigmoidf_(v.y);
                v.z = sigmoidf_(v.z); v.w = sigmoidf_(v.w);
            }
        }
        __nv_bfloat162 p0 = __float22bfloat162_rn(make_float2(v.x, v.y));
        __nv_bfloat162 p1 = __float22bfloat162_rn(make_float2(v.z, v.w));
        uint2 pk;
        pk.x = *(uint32_t*)&p0;
        pk.y = *(uint32_t*)&p1;
        *(uint2*)(Xs + r * RSTRIDE_B + c * 8) = pk;
    }
    __syncthreads();

    // ldmatrix addresses
    // A (x4, m16k16): lanes0-7 rows0-7 k+0B; 8-15 rows8-15 k+0B; 16-23 rows0-7 +16B; 24-31 rows8-15 +16B
    const uint32_t xs_u = smem_u32(Xs);
    const uint32_t ws_u = smem_u32(Ws);
    const int rowA  = ((lane & 8) ? 8 : 0) + (lane & 7);
    const int koffA = (lane & 16) ? 16 : 0;
    uint32_t aBase0 = xs_u + (uint32_t)((warpM * 32 + rowA) * RSTRIDE_B + koffA);
    uint32_t aBase1 = aBase0 + (uint32_t)(16 * RSTRIDE_B);
    // B (x4, n16k16): lanes0-7 n0-7 +0B; 8-15 n0-7 +16B; 16-23 n8-15 +0B; 24-31 n8-15 +16B
    const int nrowB  = (lane & 7) + ((lane & 16) >> 1);
    const int koffB  = (lane & 8) ? 16 : 0;
    uint32_t bBase0 = ws_u + (uint32_t)((warpN * 32 + nrowB) * RSTRIDE_B + koffB);
    uint32_t bBase1 = bBase0 + (uint32_t)(16 * RSTRIDE_B);

    float acc[2][4][4];
#pragma unroll
    for (int mt = 0; mt < 2; mt++)
#pragma unroll
        for (int nt = 0; nt < 4; nt++)
#pragma unroll
            for (int j = 0; j < 4; j++) acc[mt][nt][j] = 0.f;

    // Register double-buffered mainloop over 8 K-steps of k16 (32B each)
    uint32_t fa0[2][4], fa1[2][4], fbA[2][4], fbB[2][4];
    ldsm4(fa0[0], aBase0);
    ldsm4(fa1[0], aBase1);
    ldsm4(fbA[0], bBase0);
    ldsm4(fbB[0], bBase1);
#pragma unroll
    for (int s = 0; s < 8; s++) {
        const int cur = s & 1, nxt = cur ^ 1;
        if (s < 7) {
            uint32_t koff = (uint32_t)((s + 1) * 32);
            ldsm4(fa0[nxt], aBase0 + koff);
            ldsm4(fa1[nxt], aBase1 + koff);
            ldsm4(fbA[nxt], bBase0 + koff);
            ldsm4(fbB[nxt], bBase1 + koff);
        }
        // fbA = {n0-7.b0, n0-7.b1, n8-15.b0, n8-15.b1}; fbB = n16-31
        mma_bf16(acc[0][0], fa0[cur], &fbA[cur][0]);
        mma_bf16(acc[0][1], fa0[cur], &fbA[cur][2]);
        mma_bf16(acc[0][2], fa0[cur], &fbB[cur][0]);
        mma_bf16(acc[0][3], fa0[cur], &fbB[cur][2]);
        mma_bf16(acc[1][0], fa1[cur], &fbA[cur][0]);
        mma_bf16(acc[1][1], fa1[cur], &fbA[cur][2]);
        mma_bf16(acc[1][2], fa1[cur], &fbB[cur][0]);
        mma_bf16(acc[1][3], fa1[cur], &fbB[cur][2]);
    }

    // Epilogue: bf16x2 stores. c0,c1 -> (rq, 2kq..2kq+1); c2,c3 -> (rq+8, ..)
    const int rq = lane >> 2, kq = lane & 3;
#pragma unroll
    for (int mt = 0; mt < 2; mt++) {
        int r0 = row0 + warpM * 32 + mt * 16 + rq;
        int r1 = r0 + 8;
#pragma unroll
        for (int nt = 0; nt < 4; nt++) {
            int col = warpN * 32 + nt * 8 + 2 * kq;
            if (r0 < M)
                *(__nv_bfloat162*)(Y + (size_t)r0 * C + col) =
                    __float22bfloat162_rn(make_float2(acc[mt][nt][0], acc[mt][nt][1]));
            if (r1 < M)
                *(__nv_bfloat162*)(Y + (size_t)r1 * C + col) =
                    __float22bfloat162_rn(make_float2(acc[mt][nt][2], acc[mt][nt][3]));
        }
    }
}

// ---------------------------------------------------------------------------
// SpMM scatter-add: B[row[e], :] += val[e] * T[col[e], :]   (T is bf16)
// warp handles 8 edges (MLP=8 gathers, then 8 vector REDs)
// ---------------------------------------------------------------------------
__global__ __launch_bounds__(256) void spmm_kernel(const int* __restrict__ row,
                                                   const int* __restrict__ col,
                                                   const float* __restrict__ val,
                                                   int nnz,
                                                   const __nv_bfloat16* __restrict__ T,
                                                   float* __restrict__ Bd) {
    int warp = blockIdx.x * 8 + (threadIdx.x >> 5);
    int lane = threadIdx.x & 31;
    int e0 = warp * 8;
    if (e0 >= nnz) return;
    int cnt = nnz - e0; if (cnt > 8) cnt = 8;

    uint2 t[8]; float v[8]; float* dst[8];
#pragma unroll
    for (int j = 0; j < 8; j++) {
        if (j < cnt) {
            int e = e0 + j;
            int r = __ldg(row + e);
            int c = __ldg(col + e);
            v[j] = __ldg(val + e);
            t[j] = ((const uint2*)(T + (size_t)c * C))[lane];   // 4 bf16 = 8 bytes
            dst[j] = Bd + (size_t)r * C + lane * 4;
        }
    }
#pragma unroll
    for (int j = 0; j < 8; j++) {
        if (j < cnt) {
            float2 f0 = __bfloat1622float2(*(const __nv_bfloat162*)&t[j].x);
            float2 f1 = __bfloat1622float2(*(const __nv_bfloat162*)&t[j].y);
            float4 u = make_float4(f0.x * v[j], f0.y * v[j], f1.x * v[j], f1.y * v[j]);
            asm volatile("red.global.add.v4.f32 [%0], {%1, %2, %3, %4};"
                         :: "l"(dst[j]), "f"(u.x), "f"(u.y), "f"(u.z), "f"(u.w)
                         : "memory");
        }
    }
}

// ---------------------------------------------------------------------------
// Head: out = softmax(sigmoid(X0) @ W_out + b_out), warp per row
// ---------------------------------------------------------------------------
__global__ __launch_bounds__(256) void head_kernel(const float* __restrict__ X,
                                                   const float* __restrict__ W,
                                                   const float* __restrict__ b,
                                                   float* __restrict__ out, int M) {
    __shared__ float Ws[1280];
    __shared__ float bs[10];
    for (int i = threadIdx.x; i < 1280; i += 256) Ws[i] = W[i];
    if (threadIdx.x < 10) bs[threadIdx.x] = b[threadIdx.x];
    __syncthreads();

    int warp = (blockIdx.x * 256 + threadIdx.x) >> 5;
    int lane = threadIdx.x & 31;
    if (warp >= M) return;

    float4 xv = ((const float4*)(X + (size_t)warp * C))[lane];
    xv.x = sigmoidf_(xv.x); xv.y = sigmoidf_(xv.y);
    xv.z = sigmoidf_(xv.z); xv.w = sigmoidf_(xv.w);
    int k = lane * 4;
    float acc[10];
#pragma unroll
    for (int o = 0; o < 10; o++) {
        acc[o] = xv.x * Ws[(k + 0) * 10 + o] + xv.y * Ws[(k + 1) * 10 + o] +
                 xv.z * Ws[(k + 2) * 10 + o] + xv.w * Ws[(k + 3) * 10 + o];
    }
#pragma unroll
    for (int s = 16; s > 0; s >>= 1)
#pragma unroll
        for (int o = 0; o < 10; o++) acc[o] += __shfl_xor_sync(0xffffffffu, acc[o], s);

    float mx = -1e30f;
#pragma unroll
    for (int o = 0; o < 10; o++) { acc[o] += bs[o]; mx = fmaxf(mx, acc[o]); }
    float sum = 0.f;
    float ex[10];
#pragma unroll
    for (int o = 0; o < 10; o++) { ex[o] = __expf(acc[o] - mx); sum += ex[o]; }
    float inv = 1.f / sum;
    if (lane < 10) {
        float myv = 0.f;
#pragma unroll
        for (int o = 0; o < 10; o++)
            if (o == lane) myv = ex[o];
        out[(size_t)warp * 10 + lane] = myv * inv;
    }
}

// ---------------------------------------------------------------------------
// Host orchestration: GEMMs on stream 0, SpMMs on a forked stream, 4-deep T ring
// ---------------------------------------------------------------------------
extern "C" void kernel_launch(void* const* d_in, const int* in_sizes, int n_in,
                              void* d_out, int out_size) {
    (void)n_in; (void)out_size;

    // One-time host-side resources (created on first, uncaptured call; no device alloc)
    static cudaStream_t s1 = nullptr;
    static cudaEvent_t evFork, evJoin, evG[20], evS[20];
    if (!s1) {
        cudaStreamCreateWithFlags(&s1, cudaStreamNonBlocking);
        cudaEventCreateWithFlags(&evFork, cudaEventDisableTiming);
        cudaEventCreateWithFlags(&evJoin, cudaEventDisableTiming);
        for (int i = 0; i < 20; i++) {
            cudaEventCreateWithFlags(&evG[i], cudaEventDisableTiming);
            cudaEventCreateWithFlags(&evS[i], cudaEventDisableTiming);
        }
    }

    const float* x_in[4];
    for (int r = 0; r < 4; r++) x_in[r] = (const float*)d_in[r];
    const int*   adj_row[4]; const int* adj_col[4]; const float* adj_val[4];
    int nnz_adj[4];
    for (int r = 0; r < 4; r++) {
        adj_row[r] = (const int*)d_in[4 + 3 * r];
        adj_col[r] = (const int*)d_in[5 + 3 * r];
        adj_val[r] = (const float*)d_in[6 + 3 * r];
        nnz_adj[r] = in_sizes[4 + 3 * r];
    }
    const int*   inc_row[4]; const int* inc_col[4]; const float* inc_val[4];
    int nnz_inc[4];
    for (int k = 1; k <= 3; k++) {
        inc_row[k] = (const int*)d_in[16 + 3 * (k - 1)];
        inc_col[k] = (const int*)d_in[17 + 3 * (k - 1)];
        inc_val[k] = (const float*)d_in[18 + 3 * (k - 1)];
        nnz_inc[k] = in_sizes[16 + 3 * (k - 1)];
    }
    const float* W_same = (const float*)d_in[25];
    const float* W_h2l  = (const float*)d_in[26];
    const float* W_l2h  = (const float*)d_in[27];
    const float* W_out  = (const float*)d_in[28];
    const float* b_out  = (const float*)d_in[29];

    int N[4];
    size_t off[4];
    size_t tot = 0;
    for (int r = 0; r < 4; r++) {
        N[r] = in_sizes[r] / C;
        off[r] = tot * (size_t)C;
        tot += (size_t)N[r];
    }

    float *L0, *L1;
    __nv_bfloat16 *Tbase, *Wt;
    cudaGetSymbolAddress((void**)&L0, g_L0);
    cudaGetSymbolAddress((void**)&L1, g_L1);
    cudaGetSymbolAddress((void**)&Tbase, g_T);
    cudaGetSymbolAddress((void**)&Wt, g_Wt);
    __nv_bfloat16* Tbuf[4];
    for (int i = 0; i < 4; i++) Tbuf[i] = Tbase + (size_t)i * NMAX * C;

    cudaFuncSetAttribute(gemm_mma_kernel,
                         cudaFuncAttributeMaxDynamicSharedMemorySize, GEMM_SMEM_BYTES);

    // W transpose (stream 0, precedes all GEMMs in-order)
    wtrans_kernel<<<NWMAT, 256>>>(W_same, W_h2l, W_l2h, Wt);

    // Fork spmm stream; hoist both layer-destination memsets (hide under GEMMs)
    cudaEventRecord(evFork, 0);
    cudaStreamWaitEvent(s1, evFork, 0);
    cudaMemsetAsync(L0, 0, tot * (size_t)C * sizeof(float), s1);
    cudaMemsetAsync(L1, 0, tot * (size_t)C * sizeof(float), s1);

    int idx = 0;
    for (int l = 0; l < 2; l++) {
        const float* src[4];
        int sig = (l == 0) ? 0 : 1;
        for (int r = 0; r < 4; r++)
            src[r] = (l == 0) ? x_in[r] : (L0 + off[r]);
        float* Bcur = (l == 0) ? L0 : L1;

        // Layer-1 GEMMs read L0 which layer-0 spmms produced on s1
        if (l == 1) cudaStreamWaitEvent(0, evS[9], 0);

        for (int r = 0; r < 4; r++) {
            struct Branch { const float* x; const __nv_bfloat16* w; int M;
                            const int* er; const int* ec; const float* ev; int nnz; };
            Branch br[3]; int nb = 0;
            {   // same-rank
                br[nb++] = { src[r], Wt + (size_t)(l * 4 + r) * C * C, N[r],
                             adj_row[r], adj_col[r], adj_val[r], nnz_adj[r] };
            }
            if (r < 3) {  // high-to-low
                int k = r + 1;
                br[nb++] = { src[r + 1], Wt + (size_t)(8 + l * 3 + r) * C * C, N[r + 1],
                             inc_row[k], inc_col[k], inc_val[k], nnz_inc[k] };
            }
            if (r > 0) {  // low-to-high (transposed incidence)
                int k = r;
                br[nb++] = { src[r - 1], Wt + (size_t)(14 + l * 3 + (r - 1)) * C * C, N[r - 1],
                             inc_col[k], inc_row[k], inc_val[k], nnz_inc[k] };
            }
            for (int b = 0; b < nb; b++) {
                __nv_bfloat16* T = Tbuf[idx & 3];
                if (idx >= 4) cudaStreamWaitEvent(0, evS[idx - 4], 0);  // T reuse
                gemm_mma_kernel<<<(br[b].M + 127) / 128, 512, GEMM_SMEM_BYTES>>>(
                    br[b].x, br[b].w, T, br[b].M, sig);
                cudaEventRecord(evG[idx], 0);
                cudaStreamWaitEvent(s1, evG[idx], 0);
                spmm_kernel<<<(br[b].nnz + 63) / 64, 256, 0, s1>>>(
                    br[b].er, br[b].ec, br[b].ev, br[b].nnz, T, Bcur + off[r]);
                cudaEventRecord(evS[idx], s1);
                idx++;
            }
        }
    }

    // Join and run head
    cudaEventRecord(evJoin, s1);
    cudaStreamWaitEvent(0, evJoin, 0);
    {
        int M = N[0];
        int blocks = (M + 7) / 8;
        head_kernel<<<blocks, 256>>>(L1 + off[0], W_out, b_out, (float*)d_out, M);
    }
}

// round 14
// speedup vs baseline: 2.6523x; 1.1958x over previous
#include <cuda_runtime.h>
#include <cuda_bf16.h>
#include <cuda_fp16.h>
#include <math.h>
#include <stdint.h>

#define C 128

// Max sizes per reference: N = [40000, 120000, 80000, 20000]
#define NTOT_MAX 260000
#define NMAX     120000
#define NWMAT    20          // 8 W_same + 6 W_h2l + 6 W_l2h

// Scratch (no allocation allowed)
__device__ __half g_L0[(size_t)NTOT_MAX * C];            // layer-0 messages (fp16 accum)
__device__ __half g_L1[(size_t)NTOT_MAX * C];            // layer-1 messages (fp16 accum)
__device__ __nv_bfloat16 g_T[4][(size_t)NMAX * C];       // GEMM temp ring, bf16
__device__ __nv_bfloat16 g_Wt[(size_t)NWMAT * C * C];    // W^T, bf16

// ---------------------------------------------------------------------------
// helpers
// ---------------------------------------------------------------------------
__device__ __forceinline__ uint32_t smem_u32(const void* p) {
    uint32_t a;
    asm("{ .reg .u64 t; cvta.to.shared.u64 t, %1; cvt.u32.u64 %0, t; }" : "=r"(a) : "l"(p));
    return a;
}
__device__ __forceinline__ void mma_bf16(float* c, const uint32_t* a, const uint32_t* b) {
    asm volatile(
        "mma.sync.aligned.m16n8k16.row.col.f32.bf16.bf16.f32 "
        "{%0,%1,%2,%3}, {%4,%5,%6,%7}, {%8,%9}, {%0,%1,%2,%3};"
        : "+f"(c[0]), "+f"(c[1]), "+f"(c[2]), "+f"(c[3])
        : "r"(a[0]), "r"(a[1]), "r"(a[2]), "r"(a[3]), "r"(b[0]), "r"(b[1]));
}
__device__ __forceinline__ void ldsm4(uint32_t* r, uint32_t addr) {
    asm volatile("ldmatrix.sync.aligned.m8n8.x4.shared.b16 {%0,%1,%2,%3}, [%4];"
                 : "=r"(r[0]), "=r"(r[1]), "=r"(r[2]), "=r"(r[3]) : "r"(addr));
}
__device__ __forceinline__ float sigmoidf_(float x) { return 1.f / (1.f + __expf(-x)); }

// ---------------------------------------------------------------------------
// Transpose + bf16-convert all 20 weight matrices: Wt[m][n][k] = bf16(W_m[k][n])
// ---------------------------------------------------------------------------
__global__ void wtrans_kernel(const float* __restrict__ Ws, const float* __restrict__ Wh,
                              const float* __restrict__ Wl, __nv_bfloat16* __restrict__ Wt) {
    int m = blockIdx.x;
    const float* src;
    if (m < 8)       src = Ws + (size_t)m * C * C;
    else if (m < 14) src = Wh + (size_t)(m - 8) * C * C;
    else             src = Wl + (size_t)(m - 14) * C * C;
    __nv_bfloat16* dst = Wt + (size_t)m * C * C;
    for (int i = threadIdx.x; i < C * C; i += blockDim.x) {
        int k = i >> 7, n = i & 127;
        dst[n * C + k] = __float2bfloat16(src[i]);
    }
}

// ---------------------------------------------------------------------------
// GEMM via mma.sync bf16 + ldmatrix: Y[M,128](bf16) = act(X)[M,128] @ W[128,128]
// X is fp32 (mode=0) or fp16 with fused sigmoid (mode=1).
// CTA = 512 threads (4x4 warps), tile 128x128; warp = 32M x 32N (m16n8k16).
// __launch_bounds__(512, 2): cap regs at 64 so 2 CTAs/SM.
// ---------------------------------------------------------------------------
#define RSTRIDE_B 272
#define GEMM_SMEM_BYTES (2 * 128 * RSTRIDE_B)   // 69632

__global__ __launch_bounds__(512, 2) void gemm_mma_kernel(const void* __restrict__ Xv,
                                                          const __nv_bfloat16* __restrict__ Wt,
                                                          __nv_bfloat16* __restrict__ Y, int M,
                                                          int mode) {
    extern __shared__ char smc[];
    char* Xs = smc;                       // [row][k] bf16, stride 272B
    char* Ws = smc + 128 * RSTRIDE_B;     // [n][k]  bf16, stride 272B
    const int tid   = threadIdx.x;
    const int lane  = tid & 31;
    const int warp  = tid >> 5;
    const int warpM = warp & 3;
    const int warpN = warp >> 2;
    const int row0  = blockIdx.x * 128;

    // Stage W^T (bf16, 8B chunks = 4 bf16)
    for (int i = tid; i < 4096; i += 512) {
        int n = i >> 5, c = i & 31;
        uint2 v = ((const uint2*)(Wt + (size_t)n * C))[c];
        *(uint2*)(Ws + n * RSTRIDE_B + c * 8) = v;
    }
    // Stage X tile -> bf16 (optionally sigmoid; input fp32 or fp16 per mode)
    for (int i = tid; i < 4096; i += 512) {
        int r = i >> 5, c = i & 31;
        float4 v = make_float4(0.f, 0.f, 0.f, 0.f);
        if (row0 + r < M) {
            if (mode == 0) {
                v = ((const float4*)((const float*)Xv + (size_t)(row0 + r) * C))[c];
            } else {
                uint2 hv = ((const uint2*)((const __half*)Xv + (size_t)(row0 + r) * C))[c];
                float2 f0 = __half22float2(*(const __half2*)&hv.x);
                float2 f1 = __half22float2(*(const __half2*)&hv.y);
                v = make_float4(sigmoidf_(f0.x), sigmoidf_(f0.y),
                                sigmoidf_(f1.x), sigmoidf_(f1.y));
            }
        }
        __nv_bfloat162 p0 = __float22bfloat162_rn(make_float2(v.x, v.y));
        __nv_bfloat162 p1 = __float22bfloat162_rn(make_float2(v.z, v.w));
        uint2 pk;
        pk.x = *(uint32_t*)&p0;
        pk.y = *(uint32_t*)&p1;
        *(uint2*)(Xs + r * RSTRIDE_B + c * 8) = pk;
    }
    __syncthreads();

    // ldmatrix addresses
    const uint32_t xs_u = smem_u32(Xs);
    const uint32_t ws_u = smem_u32(Ws);
    const int rowA  = ((lane & 8) ? 8 : 0) + (lane & 7);
    const int koffA = (lane & 16) ? 16 : 0;
    uint32_t aBase0 = xs_u + (uint32_t)((warpM * 32 + rowA) * RSTRIDE_B + koffA);
    uint32_t aBase1 = aBase0 + (uint32_t)(16 * RSTRIDE_B);
    const int nrowB  = (lane & 7) + ((lane & 16) >> 1);
    const int koffB  = (lane & 8) ? 16 : 0;
    uint32_t bBase0 = ws_u + (uint32_t)((warpN * 32 + nrowB) * RSTRIDE_B + koffB);
    uint32_t bBase1 = bBase0 + (uint32_t)(16 * RSTRIDE_B);

    float acc[2][4][4];
#pragma unroll
    for (int mt = 0; mt < 2; mt++)
#pragma unroll
        for (int nt = 0; nt < 4; nt++)
#pragma unroll
            for (int j = 0; j < 4; j++) acc[mt][nt][j] = 0.f;

    // Register double-buffered mainloop over 8 K-steps of k16 (32B each)
    uint32_t fa0[2][4], fa1[2][4], fbA[2][4], fbB[2][4];
    ldsm4(fa0[0], aBase0);
    ldsm4(fa1[0], aBase1);
    ldsm4(fbA[0], bBase0);
    ldsm4(fbB[0], bBase1);
#pragma unroll
    for (int s = 0; s < 8; s++) {
        const int cur = s & 1, nxt = cur ^ 1;
        if (s < 7) {
            uint32_t koff = (uint32_t)((s + 1) * 32);
            ldsm4(fa0[nxt], aBase0 + koff);
            ldsm4(fa1[nxt], aBase1 + koff);
            ldsm4(fbA[nxt], bBase0 + koff);
            ldsm4(fbB[nxt], bBase1 + koff);
        }
        mma_bf16(acc[0][0], fa0[cur], &fbA[cur][0]);
        mma_bf16(acc[0][1], fa0[cur], &fbA[cur][2]);
        mma_bf16(acc[0][2], fa0[cur], &fbB[cur][0]);
        mma_bf16(acc[0][3], fa0[cur], &fbB[cur][2]);
        mma_bf16(acc[1][0], fa1[cur], &fbA[cur][0]);
        mma_bf16(acc[1][1], fa1[cur], &fbA[cur][2]);
        mma_bf16(acc[1][2], fa1[cur], &fbB[cur][0]);
        mma_bf16(acc[1][3], fa1[cur], &fbB[cur][2]);
    }

    // Epilogue: bf16x2 stores
    const int rq = lane >> 2, kq = lane & 3;
#pragma unroll
    for (int mt = 0; mt < 2; mt++) {
        int r0 = row0 + warpM * 32 + mt * 16 + rq;
        int r1 = r0 + 8;
#pragma unroll
        for (int nt = 0; nt < 4; nt++) {
            int col = warpN * 32 + nt * 8 + 2 * kq;
            if (r0 < M)
                *(__nv_bfloat162*)(Y + (size_t)r0 * C + col) =
                    __float22bfloat162_rn(make_float2(acc[mt][nt][0], acc[mt][nt][1]));
            if (r1 < M)
                *(__nv_bfloat162*)(Y + (size_t)r1 * C + col) =
                    __float22bfloat162_rn(make_float2(acc[mt][nt][2], acc[mt][nt][3]));
        }
    }
}

// ---------------------------------------------------------------------------
// SpMM scatter-add: B[row[e], :] += val[e] * T[col[e], :]
// T bf16, B fp16 (red.v2.f16x2). Warp = 8 edges; edge data via lane-split+shfl.
// ---------------------------------------------------------------------------
__global__ __launch_bounds__(256) void spmm_kernel(const int* __restrict__ row,
                                                   const int* __restrict__ col,
                                                   const float* __restrict__ val,
                                                   int nnz,
                                                   const __nv_bfloat16* __restrict__ T,
                                                   __half* __restrict__ Bd) {
    int warp = blockIdx.x * 8 + (threadIdx.x >> 5);
    int lane = threadIdx.x & 31;
    int e0 = warp * 8;
    if (e0 >= nnz) return;
    int cnt = nnz - e0; if (cnt > 8) cnt = 8;

    // lanes 0-7 load row, 8-15 col, 16-23 val for edges e0..e0+7
    uint32_t ed = 0;
    {
        int j = lane & 7;
        int e = e0 + j;
        if (e < nnz) {
            if (lane < 8)       ed = (uint32_t)__ldg(row + e);
            else if (lane < 16) ed = (uint32_t)__ldg(col + e);
            else if (lane < 24) ed = __float_as_uint(__ldg(val + e));
        }
    }

    uint2 t[8]; float v[8]; __half* dst[8];
#pragma unroll
    for (int j = 0; j < 8; j++) {
        if (j < cnt) {
            int r = (int)__shfl_sync(0xffffffffu, ed, j);
            int c = (int)__shfl_sync(0xffffffffu, ed, 8 + j);
            v[j] = __uint_as_float(__shfl_sync(0xffffffffu, ed, 16 + j));
            t[j] = ((const uint2*)(T + (size_t)c * C))[lane];   // 4 bf16 = 8 bytes
            dst[j] = Bd + (size_t)r * C + lane * 4;
        }
    }
#pragma unroll
    for (int j = 0; j < 8; j++) {
        if (j < cnt) {
            float2 f0 = __bfloat1622float2(*(const __nv_bfloat162*)&t[j].x);
            float2 f1 = __bfloat1622float2(*(const __nv_bfloat162*)&t[j].y);
            __half2 h0 = __float22half2_rn(make_float2(f0.x * v[j], f0.y * v[j]));
            __half2 h1 = __float22half2_rn(make_float2(f1.x * v[j], f1.y * v[j]));
            asm volatile("red.global.add.noftz.v2.f16x2 [%0], {%1, %2};"
                         :: "l"(dst[j]), "r"(*(uint32_t*)&h0), "r"(*(uint32_t*)&h1)
                         : "memory");
        }
    }
}

// ---------------------------------------------------------------------------
// Head: out = softmax(sigmoid(X0) @ W_out + b_out), warp per row; X fp16
// ---------------------------------------------------------------------------
__global__ __launch_bounds__(256) void head_kernel(const __half* __restrict__ X,
                                                   const float* __restrict__ W,
                                                   const float* __restrict__ b,
                                                   float* __restrict__ out, int M) {
    __shared__ float Ws[1280];
    __shared__ float bs[10];
    for (int i = threadIdx.x; i < 1280; i += 256) Ws[i] = W[i];
    if (threadIdx.x < 10) bs[threadIdx.x] = b[threadIdx.x];
    __syncthreads();

    int warp = (blockIdx.x * 256 + threadIdx.x) >> 5;
    int lane = threadIdx.x & 31;
    if (warp >= M) return;

    uint2 hv = ((const uint2*)(X + (size_t)warp * C))[lane];
    float2 f0 = __half22float2(*(const __half2*)&hv.x);
    float2 f1 = __half22float2(*(const __half2*)&hv.y);
    float4 xv = make_float4(sigmoidf_(f0.x), sigmoidf_(f0.y),
                            sigmoidf_(f1.x), sigmoidf_(f1.y));
    int k = lane * 4;
    float acc[10];
#pragma unroll
    for (int o = 0; o < 10; o++) {
        acc[o] = xv.x * Ws[(k + 0) * 10 + o] + xv.y * Ws[(k + 1) * 10 + o] +
                 xv.z * Ws[(k + 2) * 10 + o] + xv.w * Ws[(k + 3) * 10 + o];
    }
#pragma unroll
    for (int s = 16; s > 0; s >>= 1)
#pragma unroll
        for (int o = 0; o < 10; o++) acc[o] += __shfl_xor_sync(0xffffffffu, acc[o], s);

    float mx = -1e30f;
#pragma unroll
    for (int o = 0; o < 10; o++) { acc[o] += bs[o]; mx = fmaxf(mx, acc[o]); }
    float sum = 0.f;
    float ex[10];
#pragma unroll
    for (int o = 0; o < 10; o++) { ex[o] = __expf(acc[o] - mx); sum += ex[o]; }
    float inv = 1.f / sum;
    if (lane < 10) {
        float myv = 0.f;
#pragma unroll
        for (int o = 0; o < 10; o++)
            if (o == lane) myv = ex[o];
        out[(size_t)warp * 10 + lane] = myv * inv;
    }
}

// ---------------------------------------------------------------------------
// Host orchestration: GEMMs on stream 0, SpMMs on forked stream, 4-deep T ring,
// per-rank cross-layer dependencies.
// ---------------------------------------------------------------------------
extern "C" void kernel_launch(void* const* d_in, const int* in_sizes, int n_in,
                              void* d_out, int out_size) {
    (void)n_in; (void)out_size;

    static cudaStream_t s1 = nullptr;
    static cudaEvent_t evFork, evJoin, evG[20], evS[20];
    if (!s1) {
        cudaStreamCreateWithFlags(&s1, cudaStreamNonBlocking);
        cudaEventCreateWithFlags(&evFork, cudaEventDisableTiming);
        cudaEventCreateWithFlags(&evJoin, cudaEventDisableTiming);
        for (int i = 0; i < 20; i++) {
            cudaEventCreateWithFlags(&evG[i], cudaEventDisableTiming);
            cudaEventCreateWithFlags(&evS[i], cudaEventDisableTiming);
        }
    }

    const float* x_in[4];
    for (int r = 0; r < 4; r++) x_in[r] = (const float*)d_in[r];
    const int*   adj_row[4]; const int* adj_col[4]; const float* adj_val[4];
    int nnz_adj[4];
    for (int r = 0; r < 4; r++) {
        adj_row[r] = (const int*)d_in[4 + 3 * r];
        adj_col[r] = (const int*)d_in[5 + 3 * r];
        adj_val[r] = (const float*)d_in[6 + 3 * r];
        nnz_adj[r] = in_sizes[4 + 3 * r];
    }
    const int*   inc_row[4]; const int* inc_col[4]; const float* inc_val[4];
    int nnz_inc[4];
    for (int k = 1; k <= 3; k++) {
        inc_row[k] = (const int*)d_in[16 + 3 * (k - 1)];
        inc_col[k] = (const int*)d_in[17 + 3 * (k - 1)];
        inc_val[k] = (const float*)d_in[18 + 3 * (k - 1)];
        nnz_inc[k] = in_sizes[16 + 3 * (k - 1)];
    }
    const float* W_same = (const float*)d_in[25];
    const float* W_h2l  = (const float*)d_in[26];
    const float* W_l2h  = (const float*)d_in[27];
    const float* W_out  = (const float*)d_in[28];
    const float* b_out  = (const float*)d_in[29];

    int N[4];
    size_t off[4];
    size_t tot = 0;
    for (int r = 0; r < 4; r++) {
        N[r] = in_sizes[r] / C;
        off[r] = tot * (size_t)C;
        tot += (size_t)N[r];
    }

    __half *L0, *L1;
    __nv_bfloat16 *Tbase, *Wt;
    cudaGetSymbolAddress((void**)&L0, g_L0);
    cudaGetSymbolAddress((void**)&L1, g_L1);
    cudaGetSymbolAddress((void**)&Tbase, g_T);
    cudaGetSymbolAddress((void**)&Wt, g_Wt);
    __nv_bfloat16* Tbuf[4];
    for (int i = 0; i < 4; i++) Tbuf[i] = Tbase + (size_t)i * NMAX * C;

    cudaFuncSetAttribute(gemm_mma_kernel,
                         cudaFuncAttributeMaxDynamicSharedMemorySize, GEMM_SMEM_BYTES);

    wtrans_kernel<<<NWMAT, 256>>>(W_same, W_h2l, W_l2h, Wt);

    // Fork spmm stream; hoist destination zeroing
    cudaEventRecord(evFork, 0);
    cudaStreamWaitEvent(s1, evFork, 0);
    cudaMemsetAsync(L0, 0, tot * (size_t)C * sizeof(__half), s1);
    cudaMemsetAsync(L1, 0, tot * (size_t)C * sizeof(__half), s1);

    // Last layer-0 spmm index writing each destination rank (branch order below):
    // r0: idx 0,1 -> 1;  r1: 2,3,4 -> 4;  r2: 5,6,7 -> 7;  r3: 8,9 -> 9
    const int last0[4] = {1, 4, 7, 9};

    int idx = 0;
    for (int l = 0; l < 2; l++) {
        float* dummy;
        (void)dummy;
        const void* src[4];
        int mode = (l == 0) ? 0 : 1;
        for (int r = 0; r < 4; r++)
            src[r] = (l == 0) ? (const void*)x_in[r] : (const void*)(L0 + off[r]);
        __half* Bcur = (l == 0) ? L0 : L1;

        for (int r = 0; r < 4; r++) {
            struct Branch { const void* x; int srcRank; const __nv_bfloat16* w; int M;
                            const int* er; const int* ec; const float* ev; int nnz; };
            Branch br[3]; int nb = 0;
            {   // same-rank
                br[nb++] = { src[r], r, Wt + (size_t)(l * 4 + r) * C * C, N[r],
                             adj_row[r], adj_col[r], adj_val[r], nnz_adj[r] };
            }
            if (r < 3) {  // high-to-low
                int k = r + 1;
                br[nb++] = { src[r + 1], r + 1, Wt + (size_t)(8 + l * 3 + r) * C * C, N[r + 1],
                             inc_row[k], inc_col[k], inc_val[k], nnz_inc[k] };
            }
            if (r > 0) {  // low-to-high (transposed incidence)
                int k = r;
                br[nb++] = { src[r - 1], r - 1, Wt + (size_t)(14 + l * 3 + (r - 1)) * C * C, N[r - 1],
                             inc_col[k], inc_row[k], inc_val[k], nnz_inc[k] };
            }
            for (int b = 0; b < nb; b++) {
                __nv_bfloat16* T = Tbuf[idx & 3];
                if (idx >= 4) cudaStreamWaitEvent(0, evS[idx - 4], 0);       // T reuse
                if (l == 1)   cudaStreamWaitEvent(0, evS[last0[br[b].srcRank]], 0);  // src ready
                gemm_mma_kernel<<<(br[b].M + 127) / 128, 512, GEMM_SMEM_BYTES>>>(
                    br[b].x, br[b].w, T, br[b].M, mode);
                cudaEventRecord(evG[idx], 0);
                cudaStreamWaitEvent(s1, evG[idx], 0);
                spmm_kernel<<<(br[b].nnz + 63) / 64, 256, 0, s1>>>(
                    br[b].er, br[b].ec, br[b].ev, br[b].nnz, T, Bcur + off[r]);
                cudaEventRecord(evS[idx], s1);
                idx++;
            }
        }
    }

    // Join and run head
    cudaEventRecord(evJoin, s1);
    cudaStreamWaitEvent(0, evJoin, 0);
    {
        int M = N[0];
        int blocks = (M + 7) / 8;
        head_kernel<<<blocks, 256>>>(L1 + off[0], W_out, b_out, (float*)d_out, M);
    }
}

// round 16
// speedup vs baseline: 3.0152x; 1.1368x over previous
#include <cuda_runtime.h>
#include <cuda_bf16.h>
#include <cuda_fp16.h>
#include <math.h>
#include <stdint.h>

#define C 128

// Max sizes per reference: N = [40000, 120000, 80000, 20000]
#define NTOT_MAX 260000
#define NMAX     120000
#define NWMAT    20          // 8 W_same + 6 W_h2l + 6 W_l2h

// Scratch (no allocation allowed)
__device__ __half g_L0[(size_t)NTOT_MAX * C];            // layer-0 messages (fp16 accum)
__device__ __half g_L1[(size_t)NTOT_MAX * C];            // layer-1 messages (fp16 accum)
__device__ __nv_bfloat16 g_Xb[(size_t)NTOT_MAX * C];     // GEMM input, bf16 (act applied)
__device__ __nv_bfloat16 g_T[4][(size_t)NMAX * C];       // GEMM temp ring, bf16
__device__ __nv_bfloat16 g_Wt[(size_t)NWMAT * C * C];    // W^T, bf16

// ---------------------------------------------------------------------------
// helpers
// ---------------------------------------------------------------------------
__device__ __forceinline__ uint32_t smem_u32(const void* p) {
    uint32_t a;
    asm("{ .reg .u64 t; cvta.to.shared.u64 t, %1; cvt.u32.u64 %0, t; }" : "=r"(a) : "l"(p));
    return a;
}
__device__ __forceinline__ void mma_bf16(float* c, const uint32_t* a, const uint32_t* b) {
    asm volatile(
        "mma.sync.aligned.m16n8k16.row.col.f32.bf16.bf16.f32 "
        "{%0,%1,%2,%3}, {%4,%5,%6,%7}, {%8,%9}, {%0,%1,%2,%3};"
        : "+f"(c[0]), "+f"(c[1]), "+f"(c[2]), "+f"(c[3])
        : "r"(a[0]), "r"(a[1]), "r"(a[2]), "r"(a[3]), "r"(b[0]), "r"(b[1]));
}
__device__ __forceinline__ void ldsm4(uint32_t* r, uint32_t addr) {
    asm volatile("ldmatrix.sync.aligned.m8n8.x4.shared.b16 {%0,%1,%2,%3}, [%4];"
                 : "=r"(r[0]), "=r"(r[1]), "=r"(r[2]), "=r"(r[3]) : "r"(addr));
}
__device__ __forceinline__ float sigmoidf_(float x) { return 1.f / (1.f + __expf(-x)); }

// ---------------------------------------------------------------------------
// Transpose + bf16-convert all 20 weight matrices: Wt[m][n][k] = bf16(W_m[k][n])
// ---------------------------------------------------------------------------
__global__ void wtrans_kernel(const float* __restrict__ Ws, const float* __restrict__ Wh,
                              const float* __restrict__ Wl, __nv_bfloat16* __restrict__ Wt) {
    int m = blockIdx.x;
    const float* src;
    if (m < 8)       src = Ws + (size_t)m * C * C;
    else if (m < 14) src = Wh + (size_t)(m - 8) * C * C;
    else             src = Wl + (size_t)(m - 14) * C * C;
    __nv_bfloat16* dst = Wt + (size_t)m * C * C;
    for (int i = threadIdx.x; i < C * C; i += blockDim.x) {
        int k = i >> 7, n = i & 127;
        dst[n * C + k] = __float2bfloat16(src[i]);
    }
}

// ---------------------------------------------------------------------------
// Conversion passes: fp32 -> bf16 ; fp16 -> sigmoid -> bf16 (4 elems/thread)
// ---------------------------------------------------------------------------
__global__ void conv32_kernel(const float* __restrict__ X, __nv_bfloat16* __restrict__ Y, int n4) {
    int i = blockIdx.x * blockDim.x + threadIdx.x;
    if (i >= n4) return;
    float4 v = ((const float4*)X)[i];
    __nv_bfloat162 p0 = __float22bfloat162_rn(make_float2(v.x, v.y));
    __nv_bfloat162 p1 = __float22bfloat162_rn(make_float2(v.z, v.w));
    uint2 pk; pk.x = *(uint32_t*)&p0; pk.y = *(uint32_t*)&p1;
    ((uint2*)Y)[i] = pk;
}

__global__ void conv16sig_kernel(const __half* __restrict__ X, __nv_bfloat16* __restrict__ Y, int n4) {
    int i = blockIdx.x * blockDim.x + threadIdx.x;
    if (i >= n4) return;
    uint2 hv = ((const uint2*)X)[i];
    float2 f0 = __half22float2(*(const __half2*)&hv.x);
    float2 f1 = __half22float2(*(const __half2*)&hv.y);
    __nv_bfloat162 p0 = __float22bfloat162_rn(make_float2(sigmoidf_(f0.x), sigmoidf_(f0.y)));
    __nv_bfloat162 p1 = __float22bfloat162_rn(make_float2(sigmoidf_(f1.x), sigmoidf_(f1.y)));
    uint2 pk; pk.x = *(uint32_t*)&p0; pk.y = *(uint32_t*)&p1;
    ((uint2*)Y)[i] = pk;
}

// ---------------------------------------------------------------------------
// GEMM via mma.sync bf16 + ldmatrix: Y[M,128](bf16) = X[M,128](bf16) @ W[128,128]
// CTA = 512 threads (4x4 warps), tile 128x128; warp = 32M x 32N (m16n8k16).
// ---------------------------------------------------------------------------
#define RSTRIDE_B 272
#define GEMM_SMEM_BYTES (2 * 128 * RSTRIDE_B)   // 69632

__global__ __launch_bounds__(512, 2) void gemm_mma_kernel(const __nv_bfloat16* __restrict__ X,
                                                          const __nv_bfloat16* __restrict__ Wt,
                                                          __nv_bfloat16* __restrict__ Y, int M) {
    extern __shared__ char smc[];
    char* Xs = smc;                       // [row][k] bf16, stride 272B
    char* Ws = smc + 128 * RSTRIDE_B;     // [n][k]  bf16, stride 272B
    const int tid   = threadIdx.x;
    const int lane  = tid & 31;
    const int warp  = tid >> 5;
    const int warpM = warp & 3;
    const int warpN = warp >> 2;
    const int row0  = blockIdx.x * 128;

    // Stage W^T and X (bf16, 16B chunks; 16 chunks per 256B row)
    for (int i = tid; i < 2048; i += 512) {
        int n = i >> 4, c = i & 15;
        uint4 v = ((const uint4*)(Wt + (size_t)n * C))[c];
        *(uint4*)(Ws + n * RSTRIDE_B + c * 16) = v;
    }
    for (int i = tid; i < 2048; i += 512) {
        int r = i >> 4, c = i & 15;
        uint4 v = make_uint4(0u, 0u, 0u, 0u);
        if (row0 + r < M) v = ((const uint4*)(X + (size_t)(row0 + r) * C))[c];
        *(uint4*)(Xs + r * RSTRIDE_B + c * 16) = v;
    }
    __syncthreads();

    // ldmatrix addresses
    const uint32_t xs_u = smem_u32(Xs);
    const uint32_t ws_u = smem_u32(Ws);
    const int rowA  = ((lane & 8) ? 8 : 0) + (lane & 7);
    const int koffA = (lane & 16) ? 16 : 0;
    uint32_t aBase0 = xs_u + (uint32_t)((warpM * 32 + rowA) * RSTRIDE_B + koffA);
    uint32_t aBase1 = aBase0 + (uint32_t)(16 * RSTRIDE_B);
    const int nrowB  = (lane & 7) + ((lane & 16) >> 1);
    const int koffB  = (lane & 8) ? 16 : 0;
    uint32_t bBase0 = ws_u + (uint32_t)((warpN * 32 + nrowB) * RSTRIDE_B + koffB);
    uint32_t bBase1 = bBase0 + (uint32_t)(16 * RSTRIDE_B);

    float acc[2][4][4];
#pragma unroll
    for (int mt = 0; mt < 2; mt++)
#pragma unroll
        for (int nt = 0; nt < 4; nt++)
#pragma unroll
            for (int j = 0; j < 4; j++) acc[mt][nt][j] = 0.f;

    // Register double-buffered mainloop over 8 K-steps of k16 (32B each)
    uint32_t fa0[2][4], fa1[2][4], fbA[2][4], fbB[2][4];
    ldsm4(fa0[0], aBase0);
    ldsm4(fa1[0], aBase1);
    ldsm4(fbA[0], bBase0);
    ldsm4(fbB[0], bBase1);
#pragma unroll
    for (int s = 0; s < 8; s++) {
        const int cur = s & 1, nxt = cur ^ 1;
        if (s < 7) {
            uint32_t koff = (uint32_t)((s + 1) * 32);
            ldsm4(fa0[nxt], aBase0 + koff);
            ldsm4(fa1[nxt], aBase1 + koff);
            ldsm4(fbA[nxt], bBase0 + koff);
            ldsm4(fbB[nxt], bBase1 + koff);
        }
        mma_bf16(acc[0][0], fa0[cur], &fbA[cur][0]);
        mma_bf16(acc[0][1], fa0[cur], &fbA[cur][2]);
        mma_bf16(acc[0][2], fa0[cur], &fbB[cur][0]);
        mma_bf16(acc[0][3], fa0[cur], &fbB[cur][2]);
        mma_bf16(acc[1][0], fa1[cur], &fbA[cur][0]);
        mma_bf16(acc[1][1], fa1[cur], &fbA[cur][2]);
        mma_bf16(acc[1][2], fa1[cur], &fbB[cur][0]);
        mma_bf16(acc[1][3], fa1[cur], &fbB[cur][2]);
    }

    // Epilogue: bf16x2 stores
    const int rq = lane >> 2, kq = lane & 3;
#pragma unroll
    for (int mt = 0; mt < 2; mt++) {
        int r0 = row0 + warpM * 32 + mt * 16 + rq;
        int r1 = r0 + 8;
#pragma unroll
        for (int nt = 0; nt < 4; nt++) {
            int col = warpN * 32 + nt * 8 + 2 * kq;
            if (r0 < M)
                *(__nv_bfloat162*)(Y + (size_t)r0 * C + col) =
                    __float22bfloat162_rn(make_float2(acc[mt][nt][0], acc[mt][nt][1]));
            if (r1 < M)
                *(__nv_bfloat162*)(Y + (size_t)r1 * C + col) =
                    __float22bfloat162_rn(make_float2(acc[mt][nt][2], acc[mt][nt][3]));
        }
    }
}

// ---------------------------------------------------------------------------
// SpMM scatter-add: B[row[e], :] += val[e] * T[col[e], :]
// T bf16, B fp16 (red.v2.f16x2). Warp = 8 edges; edge data via lane-split+shfl.
// ---------------------------------------------------------------------------
__global__ __launch_bounds__(256) void spmm_kernel(const int* __restrict__ row,
                                                   const int* __restrict__ col,
                                                   const float* __restrict__ val,
                                                   int nnz,
                                                   const __nv_bfloat16* __restrict__ T,
                                                   __half* __restrict__ Bd) {
    int warp = blockIdx.x * 8 + (threadIdx.x >> 5);
    int lane = threadIdx.x & 31;
    int e0 = warp * 8;
    if (e0 >= nnz) return;
    int cnt = nnz - e0; if (cnt > 8) cnt = 8;

    uint32_t ed = 0;
    {
        int j = lane & 7;
        int e = e0 + j;
        if (e < nnz) {
            if (lane < 8)       ed = (uint32_t)__ldg(row + e);
            else if (lane < 16) ed = (uint32_t)__ldg(col + e);
            else if (lane < 24) ed = __float_as_uint(__ldg(val + e));
        }
    }

    uint2 t[8]; float v[8]; __half* dst[8];
#pragma unroll
    for (int j = 0; j < 8; j++) {
        if (j < cnt) {
            int r = (int)__shfl_sync(0xffffffffu, ed, j);
            int c = (int)__shfl_sync(0xffffffffu, ed, 8 + j);
            v[j] = __uint_as_float(__shfl_sync(0xffffffffu, ed, 16 + j));
            t[j] = ((const uint2*)(T + (size_t)c * C))[lane];
            dst[j] = Bd + (size_t)r * C + lane * 4;
        }
    }
#pragma unroll
    for (int j = 0; j < 8; j++) {
        if (j < cnt) {
            float2 f0 = __bfloat1622float2(*(const __nv_bfloat162*)&t[j].x);
            float2 f1 = __bfloat1622float2(*(const __nv_bfloat162*)&t[j].y);
            __half2 h0 = __float22half2_rn(make_float2(f0.x * v[j], f0.y * v[j]));
            __half2 h1 = __float22half2_rn(make_float2(f1.x * v[j], f1.y * v[j]));
            asm volatile("red.global.add.noftz.v2.f16x2 [%0], {%1, %2};"
                         :: "l"(dst[j]), "r"(*(uint32_t*)&h0), "r"(*(uint32_t*)&h1)
                         : "memory");
        }
    }
}

// ---------------------------------------------------------------------------
// Head: out = softmax(sigmoid(X0) @ W_out + b_out), warp per row; X fp16
// ---------------------------------------------------------------------------
__global__ __launch_bounds__(256) void head_kernel(const __half* __restrict__ X,
                                                   const float* __restrict__ W,
                                                   const float* __restrict__ b,
                                                   float* __restrict__ out, int M) {
    __shared__ float Ws[1280];
    __shared__ float bs[10];
    for (int i = threadIdx.x; i < 1280; i += 256) Ws[i] = W[i];
    if (threadIdx.x < 10) bs[threadIdx.x] = b[threadIdx.x];
    __syncthreads();

    int warp = (blockIdx.x * 256 + threadIdx.x) >> 5;
    int lane = threadIdx.x & 31;
    if (warp >= M) return;

    uint2 hv = ((const uint2*)(X + (size_t)warp * C))[lane];
    float2 f0 = __half22float2(*(const __half2*)&hv.x);
    float2 f1 = __half22float2(*(const __half2*)&hv.y);
    float4 xv = make_float4(sigmoidf_(f0.x), sigmoidf_(f0.y),
                            sigmoidf_(f1.x), sigmoidf_(f1.y));
    int k = lane * 4;
    float acc[10];
#pragma unroll
    for (int o = 0; o < 10; o++) {
        acc[o] = xv.x * Ws[(k + 0) * 10 + o] + xv.y * Ws[(k + 1) * 10 + o] +
                 xv.z * Ws[(k + 2) * 10 + o] + xv.w * Ws[(k + 3) * 10 + o];
    }
#pragma unroll
    for (int s = 16; s > 0; s >>= 1)
#pragma unroll
        for (int o = 0; o < 10; o++) acc[o] += __shfl_xor_sync(0xffffffffu, acc[o], s);

    float mx = -1e30f;
#pragma unroll
    for (int o = 0; o < 10; o++) { acc[o] += bs[o]; mx = fmaxf(mx, acc[o]); }
    float sum = 0.f;
    float ex[10];
#pragma unroll
    for (int o = 0; o < 10; o++) { ex[o] = __expf(acc[o] - mx); sum += ex[o]; }
    float inv = 1.f / sum;
    if (lane < 10) {
        float myv = 0.f;
#pragma unroll
        for (int o = 0; o < 10; o++)
            if (o == lane) myv = ex[o];
        out[(size_t)warp * 10 + lane] = myv * inv;
    }
}

// ---------------------------------------------------------------------------
// Host orchestration: GEMMs+convs on stream 0, SpMMs on forked stream,
// 4-deep T ring, per-rank cross-layer dependencies via conversion kernels.
// ---------------------------------------------------------------------------
extern "C" void kernel_launch(void* const* d_in, const int* in_sizes, int n_in,
                              void* d_out, int out_size) {
    (void)n_in; (void)out_size;

    static cudaStream_t s1 = nullptr;
    static cudaEvent_t evFork, evJoin, evG[20], evS[20];
    if (!s1) {
        cudaStreamCreateWithFlags(&s1, cudaStreamNonBlocking);
        cudaEventCreateWithFlags(&evFork, cudaEventDisableTiming);
        cudaEventCreateWithFlags(&evJoin, cudaEventDisableTiming);
        for (int i = 0; i < 20; i++) {
            cudaEventCreateWithFlags(&evG[i], cudaEventDisableTiming);
            cudaEventCreateWithFlags(&evS[i], cudaEventDisableTiming);
        }
    }

    const float* x_in[4];
    for (int r = 0; r < 4; r++) x_in[r] = (const float*)d_in[r];
    const int*   adj_row[4]; const int* adj_col[4]; const float* adj_val[4];
    int nnz_adj[4];
    for (int r = 0; r < 4; r++) {
        adj_row[r] = (const int*)d_in[4 + 3 * r];
        adj_col[r] = (const int*)d_in[5 + 3 * r];
        adj_val[r] = (const float*)d_in[6 + 3 * r];
        nnz_adj[r] = in_sizes[4 + 3 * r];
    }
    const int*   inc_row[4]; const int* inc_col[4]; const float* inc_val[4];
    int nnz_inc[4];
    for (int k = 1; k <= 3; k++) {
        inc_row[k] = (const int*)d_in[16 + 3 * (k - 1)];
        inc_col[k] = (const int*)d_in[17 + 3 * (k - 1)];
        inc_val[k] = (const float*)d_in[18 + 3 * (k - 1)];
        nnz_inc[k] = in_sizes[16 + 3 * (k - 1)];
    }
    const float* W_same = (const float*)d_in[25];
    const float* W_h2l  = (const float*)d_in[26];
    const float* W_l2h  = (const float*)d_in[27];
    const float* W_out  = (const float*)d_in[28];
    const float* b_out  = (const float*)d_in[29];

    int N[4];
    size_t off[4];
    size_t tot = 0;
    for (int r = 0; r < 4; r++) {
        N[r] = in_sizes[r] / C;
        off[r] = tot * (size_t)C;
        tot += (size_t)N[r];
    }

    __half *L0, *L1;
    __nv_bfloat16 *Xb, *Tbase, *Wt;
    cudaGetSymbolAddress((void**)&L0, g_L0);
    cudaGetSymbolAddress((void**)&L1, g_L1);
    cudaGetSymbolAddress((void**)&Xb, g_Xb);
    cudaGetSymbolAddress((void**)&Tbase, g_T);
    cudaGetSymbolAddress((void**)&Wt, g_Wt);
    __nv_bfloat16* Tbuf[4];
    for (int i = 0; i < 4; i++) Tbuf[i] = Tbase + (size_t)i * NMAX * C;

    cudaFuncSetAttribute(gemm_mma_kernel,
                         cudaFuncAttributeMaxDynamicSharedMemorySize, GEMM_SMEM_BYTES);

    wtrans_kernel<<<NWMAT, 256>>>(W_same, W_h2l, W_l2h, Wt);

    // Layer-0 input conversion fp32 -> bf16 (stream 0, in-order before GEMMs)
    for (int r = 0; r < 4; r++) {
        int n4 = N[r] * C / 4;
        conv32_kernel<<<(n4 + 255) / 256, 256>>>(x_in[r], Xb + off[r], n4);
    }

    // Fork spmm stream; hoist destination zeroing
    cudaEventRecord(evFork, 0);
    cudaStreamWaitEvent(s1, evFork, 0);
    cudaMemsetAsync(L0, 0, tot * (size_t)C * sizeof(__half), s1);
    cudaMemsetAsync(L1, 0, tot * (size_t)C * sizeof(__half), s1);

    // Last layer-0 spmm index writing each destination rank (branch order below):
    // r0: idx 0,1 -> 1;  r1: 2,3,4 -> 4;  r2: 5,6,7 -> 7;  r3: 8,9 -> 9
    const int last0[4] = {1, 4, 7, 9};

    int idx = 0;
    for (int l = 0; l < 2; l++) {
        __half* Bcur = (l == 0) ? L0 : L1;

        if (l == 1) {
            // Convert sigmoid(L0_r) -> Xb_r per rank, gated on that rank's last spmm
            for (int r = 0; r < 4; r++) {
                cudaStreamWaitEvent(0, evS[last0[r]], 0);
                int n4 = N[r] * C / 4;
                conv16sig_kernel<<<(n4 + 255) / 256, 256>>>(L0 + off[r], Xb + off[r], n4);
            }
        }

        for (int r = 0; r < 4; r++) {
            struct Branch { size_t xoff; const __nv_bfloat16* w; int M;
                            const int* er; const int* ec; const float* ev; int nnz; };
            Branch br[3]; int nb = 0;
            {   // same-rank
                br[nb++] = { off[r], Wt + (size_t)(l * 4 + r) * C * C, N[r],
                             adj_row[r], adj_col[r], adj_val[r], nnz_adj[r] };
            }
            if (r < 3) {  // high-to-low
                int k = r + 1;
                br[nb++] = { off[r + 1], Wt + (size_t)(8 + l * 3 + r) * C * C, N[r + 1],
                             inc_row[k], inc_col[k], inc_val[k], nnz_inc[k] };
            }
            if (r > 0) {  // low-to-high (transposed incidence)
                int k = r;
                br[nb++] = { off[r - 1], Wt + (size_t)(14 + l * 3 + (r - 1)) * C * C, N[r - 1],
                             inc_col[k], inc_row[k], inc_val[k], nnz_inc[k] };
            }
            for (int b = 0; b < nb; b++) {
                __nv_bfloat16* T = Tbuf[idx & 3];
                if (idx >= 4) cudaStreamWaitEvent(0, evS[idx - 4], 0);   // T reuse
                gemm_mma_kernel<<<(br[b].M + 127) / 128, 512, GEMM_SMEM_BYTES>>>(
                    Xb + br[b].xoff, br[b].w, T, br[b].M);
                cudaEventRecord(evG[idx], 0);
                cudaStreamWaitEvent(s1, evG[idx], 0);
                spmm_kernel<<<(br[b].nnz + 63) / 64, 256, 0, s1>>>(
                    br[b].er, br[b].ec, br[b].ev, br[b].nnz, T, Bcur + off[r]);
                cudaEventRecord(evS[idx], s1);
                idx++;
            }
        }
    }

    // Join and run head
    cudaEventRecord(evJoin, s1);
    cudaStreamWaitEvent(0, evJoin, 0);
    {
        int M = N[0];
        int blocks = (M + 7) / 8;
        head_kernel<<<blocks, 256>>>(L1 + off[0], W_out, b_out, (float*)d_out, M);
    }
}